// round 5
// baseline (speedup 1.0000x reference)
#include <cuda_runtime.h>

// Problem constants
#define Bq    16384
#define Dd    128
#define Hh    4
#define Ee    8
#define Nn    65536        // B*H tokens
#define OD    32           // ODIM = D/H
#define NSLOT 131072       // Nn * TOPK
#define NGB   512          // gating blocks (128 tokens each)

// ---------------- device scratch (no allocs allowed) ----------------
__device__ float g_tok [Nn * Dd];      // 32 MB : query tokens [N,128]
__device__ float g_gate[Nn * Dd];      // 32 MB : gate tokens  [N,128]
__device__ int   g_topi [NSLOT];
__device__ float g_topw [NSLOT];
__device__ int   g_srank[NSLOT];       // rank within gating block per (token,slot)
__device__ int   g_blkcnt [NGB * Ee];
__device__ int   g_blkbase[NGB * Ee];  // per-expert exclusive prefix over blocks
__device__ int   g_off[Ee + 1];
__device__ int   g_count[Ee];
__device__ int   g_tileoff[Ee + 1];
__device__ float g_sump[Ee];
__device__ int   g_cnt1[Ee];
__device__ float g_aux;
__device__ int   g_perm[NSLOT];        // expert-sorted list of (token*2+slot)
__device__ float g_ys[(size_t)NSLOT * OD]; // 16 MB per-slot weighted expert outputs

// ---------------- init ----------------
__global__ void k_init() {
    int t = threadIdx.x;
    if (t < Ee) { g_sump[t] = 0.f; g_cnt1[t] = 0; }
}

// ---------------- projection GEMM: out[16384,512] = X[16384,128] @ W[128,512] + b ----
// block tile 128(M) x 64(N), K=128 fully smem-resident. 256 threads, 8x4 micro.
__global__ void k_proj(const float* __restrict__ X, const float* __restrict__ W,
                       const float* __restrict__ bias, float* __restrict__ out) {
    extern __shared__ float sm[];
    float* As = sm;               // 128 x 132 (pad keeps 2 ty-groups on distinct banks)
    float* Bs = sm + 128 * 132;   // 128 x 64
    const int tid = threadIdx.x;
    const int m0 = blockIdx.y * 128;
    const int n0 = blockIdx.x * 64;

    for (int i = tid; i < 128 * 32; i += 256) {
        int r = i >> 5, c = (i & 31) << 2;
        *(float4*)(As + r * 132 + c) = *(const float4*)(X + (size_t)(m0 + r) * Dd + c);
    }
    for (int i = tid; i < 128 * 16; i += 256) {
        int r = i >> 4, c = (i & 15) << 2;
        *(float4*)(Bs + r * 64 + c) = *(const float4*)(W + (size_t)r * 512 + n0 + c);
    }
    __syncthreads();

    const int tx = tid & 15, ty = tid >> 4;
    float acc[8][4];
#pragma unroll
    for (int i = 0; i < 8; i++)
#pragma unroll
        for (int j = 0; j < 4; j++) acc[i][j] = 0.f;

    const float* Ap = As + ty * 132;   // rows ty + 16*i  (bank-friendly interleave)
    const float* Bp = Bs + tx * 4;
#pragma unroll 8
    for (int k = 0; k < 128; k++) {
        float4 b = *(const float4*)(Bp + k * 64);
#pragma unroll
        for (int i = 0; i < 8; i++) {
            float a = Ap[(i * 16) * 132 + k];
            acc[i][0] = fmaf(a, b.x, acc[i][0]);
            acc[i][1] = fmaf(a, b.y, acc[i][1]);
            acc[i][2] = fmaf(a, b.z, acc[i][2]);
            acc[i][3] = fmaf(a, b.w, acc[i][3]);
        }
    }
    float4 bv = *(const float4*)(bias + n0 + tx * 4);
#pragma unroll
    for (int i = 0; i < 8; i++) {
        int m = m0 + ty + i * 16;
        float4 o;
        o.x = acc[i][0] + bv.x; o.y = acc[i][1] + bv.y;
        o.z = acc[i][2] + bv.z; o.w = acc[i][3] + bv.w;
        *(float4*)(out + (size_t)m * 512 + n0 + tx * 4) = o;
    }
}

// ---------------- gating: softmax over 8 logits, top-2, ranks + aux stats ----------
// 512 blocks x 256 threads; warp per token, 16 tokens per warp.
__global__ void k_gate(const float* __restrict__ Wg) {
    __shared__ int   srank[Ee];
    __shared__ float ssum [Ee];
    __shared__ int   scnt1[Ee];
    const int tid = threadIdx.x;
    if (tid < Ee) { srank[tid] = 0; ssum[tid] = 0.f; scnt1[tid] = 0; }
    __syncthreads();

    const int lane = tid & 31, warp = tid >> 5;
    float wr[4][8];
#pragma unroll
    for (int i = 0; i < 4; i++)
#pragma unroll
        for (int e = 0; e < 8; e++)
            wr[i][e] = Wg[(lane * 4 + i) * 8 + e];

    float lsum[8];
#pragma unroll
    for (int e = 0; e < 8; e++) lsum[e] = 0.f;

    const int wg = blockIdx.x * 8 + warp;
    for (int it = 0; it < 16; it++) {
        int n = wg * 16 + it;
        float4 gv = *(const float4*)(g_gate + (size_t)n * 128 + lane * 4);
        float p[8];
#pragma unroll
        for (int e = 0; e < 8; e++)
            p[e] = gv.x * wr[0][e] + gv.y * wr[1][e] + gv.z * wr[2][e] + gv.w * wr[3][e];
#pragma unroll
        for (int off = 16; off; off >>= 1)
#pragma unroll
            for (int e = 0; e < 8; e++)
                p[e] += __shfl_xor_sync(0xffffffffu, p[e], off);
        // softmax
        float mx = p[0];
#pragma unroll
        for (int e = 1; e < 8; e++) mx = fmaxf(mx, p[e]);
        float s = 0.f;
#pragma unroll
        for (int e = 0; e < 8; e++) { p[e] = __expf(p[e] - mx); s += p[e]; }
        float inv = 1.f / s;
#pragma unroll
        for (int e = 0; e < 8; e++) p[e] *= inv;
        // top-2 (ties -> lowest index, matching lax.top_k)
        int i1 = 0; float v1 = p[0];
#pragma unroll
        for (int e = 1; e < 8; e++) if (p[e] > v1) { v1 = p[e]; i1 = e; }
        int i2 = -1; float v2 = -1e30f;
#pragma unroll
        for (int e = 0; e < 8; e++) if (e != i1 && p[e] > v2) { v2 = p[e]; i2 = e; }
#pragma unroll
        for (int e = 0; e < 8; e++) lsum[e] += p[e];

        if (lane == 0) {
            atomicAdd(&scnt1[i1], 1);
            int r1 = atomicAdd(&srank[i1], 1);
            int r2 = atomicAdd(&srank[i2], 1);
            float wsum = v1 + v2;
            g_topi[2 * n]     = i1;  g_topi[2 * n + 1] = i2;
            g_topw[2 * n]     = v1 / wsum;
            g_topw[2 * n + 1] = v2 / wsum;
            g_srank[2 * n]     = r1;
            g_srank[2 * n + 1] = r2;
        }
    }
    if (lane == 0)
#pragma unroll
        for (int e = 0; e < 8; e++) atomicAdd(&ssum[e], lsum[e]);
    __syncthreads();
    if (tid < Ee) {
        g_blkcnt[blockIdx.x * Ee + tid] = srank[tid];
        atomicAdd(&g_sump[tid], ssum[tid]);
        atomicAdd(&g_cnt1[tid], scnt1[tid]);
    }
}

// ---------------- phase2: prefix sums, offsets, tile map, aux loss ----------------
__global__ void k_phase2() {
    const int tid = threadIdx.x;
    if (tid < Ee) {
        int base = 0;
        for (int b = 0; b < NGB; b++) {
            int c = g_blkcnt[b * Ee + tid];
            g_blkbase[b * Ee + tid] = base;
            base += c;
        }
        g_count[tid] = base;
    }
    __syncthreads();
    if (tid == 0) {
        int off = 0, toff = 0;
        for (int e = 0; e < Ee; e++) {
            g_off[e] = off; g_tileoff[e] = toff;
            off  += g_count[e];
            toff += (g_count[e] + 63) >> 6;
        }
        g_off[Ee] = off; g_tileoff[Ee] = toff;
        float aux = 0.f;
        for (int e = 0; e < Ee; e++)
            aux += (float)g_cnt1[e] * g_sump[e];
        g_aux = (float)Ee * aux / ((float)Nn * (float)Nn);
    }
}

// ---------------- scatter tokens into expert-sorted list ----------------
__global__ void k_scatter() {
    int idx = blockIdx.x * blockDim.x + threadIdx.x;
    if (idx >= NSLOT) return;
    int e = g_topi[idx];
    int n = idx >> 1;
    int pos = g_off[e] + g_blkbase[(n >> 7) * Ee + e] + g_srank[idx];
    g_perm[pos] = idx;
}

// ---------------- fused expert MLP: gather -> GEMM1+ReLU -> GEMM2 -> weighted store
// one CTA = 64 (token,slot) entries of one expert. 256 threads.
__global__ void k_expert(const float* __restrict__ W1, const float* __restrict__ b1,
                         const float* __restrict__ W2, const float* __restrict__ b2) {
    extern __shared__ float sm[];
    float* As  = sm;                   // 64 x 132 : tokens, later reused for h
    float* W1s = sm + 8448;            // 64 x 128 : W1 k-chunk
    float* W2s = sm + 8448 + 8192;     // 128 x 32
    int*   sEnc = (int*)(sm + 20736);  // 64
    float* sW   = sm + 20800;          // 64
    const int tid = threadIdx.x;

    const int t = blockIdx.x;
    if (t >= g_tileoff[Ee]) return;
    int e = 0;
#pragma unroll
    for (int i = 0; i < Ee - 1; i++)
        if (t >= g_tileoff[e + 1]) e++;
    const int tile = t - g_tileoff[e];
    const int i0 = tile << 6;
    const int nvalid = min(64, g_count[e] - i0);

    if (tid < 64) {
        int j = g_off[e] + i0 + tid;
        if (j > NSLOT - 1) j = NSLOT - 1;   // tail rows: safe garbage, never stored
        int enc = g_perm[j];
        sEnc[tid] = enc;
        sW[tid]   = g_topw[enc];
    }
    __syncthreads();

    for (int i = tid; i < 64 * 32; i += 256) {
        int r = i >> 5, c = (i & 31) << 2;
        *(float4*)(As + r * 132 + c) =
            *(const float4*)(g_tok + (size_t)(sEnc[r] >> 1) * 128 + c);
    }
    const float* W2e = W2 + (size_t)e * Dd * OD;
    for (int i = tid; i < 1024; i += 256)
        ((float4*)W2s)[i] = ((const float4*)W2e)[i];

    const int tx = tid & 15, ty = tid >> 4;
    float acc[4][8];
#pragma unroll
    for (int i = 0; i < 4; i++)
#pragma unroll
        for (int j = 0; j < 8; j++) acc[i][j] = 0.f;

    const float* W1e = W1 + (size_t)e * Dd * Dd;
#pragma unroll
    for (int kc = 0; kc < 2; kc++) {
        for (int i = tid; i < 64 * 32; i += 256) {
            int r = i >> 5, c = (i & 31) << 2;
            *(float4*)(W1s + r * 128 + c) =
                *(const float4*)(W1e + (size_t)(kc * 64 + r) * 128 + c);
        }
        __syncthreads();
#pragma unroll 8
        for (int kk = 0; kk < 64; kk++) {
            int k = kc * 64 + kk;
            float4 b0 = *(const float4*)(W1s + kk * 128 + tx * 8);
            float4 b1v = *(const float4*)(W1s + kk * 128 + tx * 8 + 4);
#pragma unroll
            for (int i = 0; i < 4; i++) {
                float a = As[(ty * 4 + i) * 132 + k];
                acc[i][0] = fmaf(a, b0.x, acc[i][0]);
                acc[i][1] = fmaf(a, b0.y, acc[i][1]);
                acc[i][2] = fmaf(a, b0.z, acc[i][2]);
                acc[i][3] = fmaf(a, b0.w, acc[i][3]);
                acc[i][4] = fmaf(a, b1v.x, acc[i][4]);
                acc[i][5] = fmaf(a, b1v.y, acc[i][5]);
                acc[i][6] = fmaf(a, b1v.z, acc[i][6]);
                acc[i][7] = fmaf(a, b1v.w, acc[i][7]);
            }
        }
        __syncthreads();
    }

    // h = relu(acc + b1), stored back into As (token data no longer needed)
    float bb[8];
    const float* b1e = b1 + e * Dd;
#pragma unroll
    for (int j = 0; j < 8; j++) bb[j] = b1e[tx * 8 + j];
#pragma unroll
    for (int i = 0; i < 4; i++) {
        int r = ty * 4 + i;
        float4 h0, h1;
        h0.x = fmaxf(acc[i][0] + bb[0], 0.f);
        h0.y = fmaxf(acc[i][1] + bb[1], 0.f);
        h0.z = fmaxf(acc[i][2] + bb[2], 0.f);
        h0.w = fmaxf(acc[i][3] + bb[3], 0.f);
        h1.x = fmaxf(acc[i][4] + bb[4], 0.f);
        h1.y = fmaxf(acc[i][5] + bb[5], 0.f);
        h1.z = fmaxf(acc[i][6] + bb[6], 0.f);
        h1.w = fmaxf(acc[i][7] + bb[7], 0.f);
        *(float4*)(As + r * 132 + tx * 8)     = h0;
        *(float4*)(As + r * 132 + tx * 8 + 4) = h1;
    }
    __syncthreads();

    // GEMM2: eo[64,32] = h[64,128] @ W2[128,32]
    const int tx2 = tid & 7, ty2 = tid >> 3;   // 8 x 32 layout, 2 rows x 4 cols each
    float acc2[2][4];
#pragma unroll
    for (int i = 0; i < 2; i++)
#pragma unroll
        for (int j = 0; j < 4; j++) acc2[i][j] = 0.f;
#pragma unroll 8
    for (int k = 0; k < 128; k++) {
        float4 w = *(const float4*)(W2s + k * 32 + tx2 * 4);
        float h0 = As[(ty2 * 2) * 132 + k];
        float h1 = As[(ty2 * 2 + 1) * 132 + k];
        acc2[0][0] = fmaf(h0, w.x, acc2[0][0]);
        acc2[0][1] = fmaf(h0, w.y, acc2[0][1]);
        acc2[0][2] = fmaf(h0, w.z, acc2[0][2]);
        acc2[0][3] = fmaf(h0, w.w, acc2[0][3]);
        acc2[1][0] = fmaf(h1, w.x, acc2[1][0]);
        acc2[1][1] = fmaf(h1, w.y, acc2[1][1]);
        acc2[1][2] = fmaf(h1, w.z, acc2[1][2]);
        acc2[1][3] = fmaf(h1, w.w, acc2[1][3]);
    }
    float bc[4];
    const float* b2e = b2 + e * OD;
#pragma unroll
    for (int j = 0; j < 4; j++) bc[j] = b2e[tx2 * 4 + j];
#pragma unroll
    for (int i = 0; i < 2; i++) {
        int r = ty2 * 2 + i;
        if (r < nvalid) {
            int enc = sEnc[r];
            float w = sW[r];
            float4 o;
            o.x = (acc2[i][0] + bc[0]) * w;
            o.y = (acc2[i][1] + bc[1]) * w;
            o.z = (acc2[i][2] + bc[2]) * w;
            o.w = (acc2[i][3] + bc[3]) * w;
            *(float4*)(g_ys + (size_t)enc * 32 + tx2 * 4) = o;
        }
    }
}

// ---------------- final: out[b] = sum_j y_flat[b][j] * Wout[j] + bout ----------------
__global__ void k_final(const float* __restrict__ Wout, const float* __restrict__ bout,
                        float* __restrict__ out, int out_size) {
    const int tid = threadIdx.x, lane = tid & 31, warp = tid >> 5;
    const int b = blockIdx.x * 8 + warp;
    const int j = lane * 4;
    const int n = b * 4 + (j >> 5);
    const int o = j & 31;
    float4 y0 = *(const float4*)(g_ys + (size_t)(n * 2) * 32 + o);
    float4 y1 = *(const float4*)(g_ys + (size_t)(n * 2 + 1) * 32 + o);
    float4 wv = *(const float4*)(Wout + j);
    float s = (y0.x + y1.x) * wv.x + (y0.y + y1.y) * wv.y +
              (y0.z + y1.z) * wv.z + (y0.w + y1.w) * wv.w;
#pragma unroll
    for (int off = 16; off; off >>= 1) s += __shfl_xor_sync(0xffffffffu, s, off);
    if (lane == 0) out[b] = s + bout[0];
    if (blockIdx.x == 0 && tid == 0)
        for (int i = Bq; i < out_size; i++) out[i] = g_aux;   // aux loss scalar
}

// ---------------- launch ----------------
extern "C" void kernel_launch(void* const* d_in, const int* in_sizes, int n_in,
                              void* d_out, int out_size) {
    const float* x    = (const float*)d_in[0];
    const float* Wq   = (const float*)d_in[1];
    const float* bq   = (const float*)d_in[2];
    const float* Wk   = (const float*)d_in[3];
    const float* bk   = (const float*)d_in[4];
    const float* Wg   = (const float*)d_in[5];
    const float* W1   = (const float*)d_in[6];
    const float* b1   = (const float*)d_in[7];
    const float* W2   = (const float*)d_in[8];
    const float* b2   = (const float*)d_in[9];
    const float* Wout = (const float*)d_in[10];
    const float* bout = (const float*)d_in[11];
    float* out = (float*)d_out;

    const int smProj = (128 * 132 + 128 * 64) * 4;  // 100,352 B
    const int smExp  = 20864 * 4;                   // 83,456 B
    cudaFuncSetAttribute(k_proj,   cudaFuncAttributeMaxDynamicSharedMemorySize, smProj);
    cudaFuncSetAttribute(k_expert, cudaFuncAttributeMaxDynamicSharedMemorySize, smExp);

    void* ptok = nullptr; void* pgate = nullptr;
    cudaGetSymbolAddress(&ptok,  g_tok);
    cudaGetSymbolAddress(&pgate, g_gate);

    k_init<<<1, 32>>>();
    dim3 gp(8, 128);
    k_proj<<<gp, 256, smProj>>>(x, Wq, bq, (float*)ptok);
    k_proj<<<gp, 256, smProj>>>(x, Wk, bk, (float*)pgate);
    k_gate<<<NGB, 256>>>(Wg);
    k_phase2<<<1, 64>>>();
    k_scatter<<<NSLOT / 256, 256>>>();
    k_expert<<<2056, 256, smExp>>>(W1, b1, W2, b2);
    k_final<<<Bq / 8, 256>>>(Wout, bout, out, out_size);
}

// round 6
// speedup vs baseline: 1.4852x; 1.4852x over previous
#include <cuda_runtime.h>

// Problem constants
#define Bq    16384
#define Dd    128
#define Hh    4
#define Ee    8
#define Nn    65536        // B*H tokens
#define OD    32           // ODIM = D/H
#define NSLOT 131072       // Nn * TOPK
#define NGB   512          // gating blocks (128 tokens each)
#define NBIN  32           // (expert, head) bins

// ---------------- device scratch (no allocs allowed) ----------------
__device__ float g_gate[Nn * Dd];        // 32 MB : gate tokens  [N,128]
__device__ float g_M [NBIN * Dd * Dd];   // 2 MB  : folded Wq_h @ W1_e per (e,h)
__device__ float g_bM[NBIN * Dd];        // folded bias (bq_h @ W1_e + b1_e)
__device__ float g_v [NBIN * Dd];        // W2_e @ Wout_chunk_h
__device__ float g_c [NBIN];             // b2_e . Wout_chunk_h
__device__ int   g_topi [NSLOT];
__device__ float g_topw [NSLOT];
__device__ int   g_srank[NSLOT];         // rank within gating block per (token,slot)
__device__ int   g_blkcnt [NGB * NBIN];
__device__ int   g_blkbase[NGB * NBIN];  // per-bin exclusive prefix over blocks
__device__ int   g_off[NBIN + 1];
__device__ int   g_count[NBIN];
__device__ int   g_tileoff[NBIN + 1];
__device__ float g_sump[Ee];
__device__ int   g_cnt1[Ee];
__device__ float g_aux;
__device__ int   g_perm[NSLOT];          // bin-sorted list of (token*2+slot)
__device__ float g_contrib[NSLOT];       // per-slot weighted scalar contribution

// ---------------- init ----------------
__global__ void k_init() {
    int t = threadIdx.x;
    if (t < Ee) { g_sump[t] = 0.f; g_cnt1[t] = 0; }
}

// ---------------- fold: M[e*4+h] = Wq_h(128x128) @ W1_e(128x128) ----------------
// 64 blocks: (eh, half). 256 threads, 8x4 micro over a 128x64 output tile.
__global__ void k_fold(const float* __restrict__ Wq, const float* __restrict__ W1) {
    extern __shared__ float sm[];
    float* As = sm;               // 128 x 132 : Wq_h  (rows c, cols j)
    float* Bs = sm + 128 * 132;   // 128 x 64  : W1_e  (rows j, cols k-slice)
    const int tid = threadIdx.x;
    const int bb = blockIdx.x;
    const int eh = bb >> 1;
    const int e  = eh >> 2, h = eh & 3;
    const int n0 = (bb & 1) * 64;

    for (int i = tid; i < 128 * 32; i += 256) {
        int r = i >> 5, c = (i & 31) << 2;
        *(float4*)(As + r * 132 + c) = *(const float4*)(Wq + (size_t)r * 512 + h * 128 + c);
    }
    for (int i = tid; i < 128 * 16; i += 256) {
        int r = i >> 4, c = (i & 15) << 2;
        *(float4*)(Bs + r * 64 + c) =
            *(const float4*)(W1 + (size_t)e * 16384 + (size_t)r * 128 + n0 + c);
    }
    __syncthreads();

    const int tx = tid & 15, ty = tid >> 4;
    float acc[8][4];
#pragma unroll
    for (int i = 0; i < 8; i++)
#pragma unroll
        for (int j = 0; j < 4; j++) acc[i][j] = 0.f;

#pragma unroll 8
    for (int k = 0; k < 128; k++) {
        float4 b = *(const float4*)(Bs + k * 64 + tx * 4);
#pragma unroll
        for (int i = 0; i < 8; i++) {
            float a = As[(ty + 16 * i) * 132 + k];
            acc[i][0] = fmaf(a, b.x, acc[i][0]);
            acc[i][1] = fmaf(a, b.y, acc[i][1]);
            acc[i][2] = fmaf(a, b.z, acc[i][2]);
            acc[i][3] = fmaf(a, b.w, acc[i][3]);
        }
    }
#pragma unroll
    for (int i = 0; i < 8; i++) {
        int m = ty + 16 * i;
        *(float4*)(g_M + (size_t)eh * 16384 + (size_t)m * 128 + n0 + tx * 4) =
            *(float4*)acc[i];
    }
}

// ---------------- fold small: bM, v, c per (e,h) ----------------
__global__ void k_fold_small(const float* __restrict__ bq, const float* __restrict__ W1,
                             const float* __restrict__ b1, const float* __restrict__ W2,
                             const float* __restrict__ b2, const float* __restrict__ Wout) {
    const int eh = blockIdx.x;
    const int e = eh >> 2, h = eh & 3;
    const int k = threadIdx.x;   // 0..127
    // bM[eh][k] = b1[e][k] + sum_j bq[h*128+j] * W1[e][j][k]
    float s = b1[e * 128 + k];
    for (int j = 0; j < 128; j++)
        s = fmaf(bq[h * 128 + j], W1[(size_t)e * 16384 + (size_t)j * 128 + k], s);
    g_bM[eh * 128 + k] = s;
    // v[eh][j] = sum_t W2[e][j][t] * Wout[h*32+t]   (NTASK = 1)
    float v = 0.f;
    for (int t = 0; t < 32; t++)
        v = fmaf(W2[(size_t)e * 4096 + (size_t)k * 32 + t], Wout[h * 32 + t], v);
    g_v[eh * 128 + k] = v;
    if (k == 0) {
        float c = 0.f;
        for (int t = 0; t < 32; t++)
            c = fmaf(b2[e * 32 + t], Wout[h * 32 + t], c);
        g_c[eh] = c;
    }
}

// ---------------- projection GEMM: out[16384,512] = X @ W + b ----------------
// block tile 128(M) x 128(N), K=128; B staged in two 64-k chunks. 8x8 micro.
__global__ void __launch_bounds__(256, 2)
k_proj(const float* __restrict__ X, const float* __restrict__ W,
       const float* __restrict__ bias, float* __restrict__ out) {
    extern __shared__ float sm[];
    float* As = sm;               // 128 x 132
    float* Bs = sm + 128 * 132;   // 64 x 128
    const int tid = threadIdx.x;
    const int m0 = blockIdx.y * 128;
    const int n0 = blockIdx.x * 128;

    for (int i = tid; i < 128 * 32; i += 256) {
        int r = i >> 5, c = (i & 31) << 2;
        *(float4*)(As + r * 132 + c) = *(const float4*)(X + (size_t)(m0 + r) * Dd + c);
    }

    const int tx = tid & 15, ty = tid >> 4;
    float acc[8][8];
#pragma unroll
    for (int i = 0; i < 8; i++)
#pragma unroll
        for (int j = 0; j < 8; j++) acc[i][j] = 0.f;

#pragma unroll
    for (int kc = 0; kc < 2; kc++) {
        for (int i = tid; i < 64 * 32; i += 256) {
            int r = i >> 5, c = (i & 31) << 2;
            *(float4*)(Bs + r * 128 + c) =
                *(const float4*)(W + (size_t)(kc * 64 + r) * 512 + n0 + c);
        }
        __syncthreads();
#pragma unroll 8
        for (int kk = 0; kk < 64; kk++) {
            float4 b0 = *(const float4*)(Bs + kk * 128 + tx * 8);
            float4 b1v = *(const float4*)(Bs + kk * 128 + tx * 8 + 4);
            int k = kc * 64 + kk;
#pragma unroll
            for (int i = 0; i < 8; i++) {
                float a = As[(ty + 16 * i) * 132 + k];
                acc[i][0] = fmaf(a, b0.x, acc[i][0]);
                acc[i][1] = fmaf(a, b0.y, acc[i][1]);
                acc[i][2] = fmaf(a, b0.z, acc[i][2]);
                acc[i][3] = fmaf(a, b0.w, acc[i][3]);
                acc[i][4] = fmaf(a, b1v.x, acc[i][4]);
                acc[i][5] = fmaf(a, b1v.y, acc[i][5]);
                acc[i][6] = fmaf(a, b1v.z, acc[i][6]);
                acc[i][7] = fmaf(a, b1v.w, acc[i][7]);
            }
        }
        __syncthreads();
    }
    float4 bv0 = *(const float4*)(bias + n0 + tx * 8);
    float4 bv1 = *(const float4*)(bias + n0 + tx * 8 + 4);
#pragma unroll
    for (int i = 0; i < 8; i++) {
        int m = m0 + ty + 16 * i;
        float4 o0, o1;
        o0.x = acc[i][0] + bv0.x; o0.y = acc[i][1] + bv0.y;
        o0.z = acc[i][2] + bv0.z; o0.w = acc[i][3] + bv0.w;
        o1.x = acc[i][4] + bv1.x; o1.y = acc[i][5] + bv1.y;
        o1.z = acc[i][6] + bv1.z; o1.w = acc[i][7] + bv1.w;
        *(float4*)(out + (size_t)m * 512 + n0 + tx * 8)     = o0;
        *(float4*)(out + (size_t)m * 512 + n0 + tx * 8 + 4) = o1;
    }
}

// ---------------- gating: softmax over 8 logits, top-2, (e,h)-bin ranks + aux ------
// 512 blocks x 256 threads; warp per token, 16 tokens per warp.
__global__ void k_gate(const float* __restrict__ Wg) {
    __shared__ int   srank[NBIN];
    __shared__ float ssum [Ee];
    __shared__ int   scnt1[Ee];
    const int tid = threadIdx.x;
    if (tid < NBIN) srank[tid] = 0;
    if (tid < Ee) { ssum[tid] = 0.f; scnt1[tid] = 0; }
    __syncthreads();

    const int lane = tid & 31, warp = tid >> 5;
    float wr[4][8];
#pragma unroll
    for (int i = 0; i < 4; i++)
#pragma unroll
        for (int e = 0; e < 8; e++)
            wr[i][e] = Wg[(lane * 4 + i) * 8 + e];

    float lsum[8];
#pragma unroll
    for (int e = 0; e < 8; e++) lsum[e] = 0.f;

    const int wg = blockIdx.x * 8 + warp;
    for (int it = 0; it < 16; it++) {
        int n = wg * 16 + it;
        float4 gv = *(const float4*)(g_gate + (size_t)n * 128 + lane * 4);
        float p[8];
#pragma unroll
        for (int e = 0; e < 8; e++)
            p[e] = gv.x * wr[0][e] + gv.y * wr[1][e] + gv.z * wr[2][e] + gv.w * wr[3][e];
#pragma unroll
        for (int off = 16; off; off >>= 1)
#pragma unroll
            for (int e = 0; e < 8; e++)
                p[e] += __shfl_xor_sync(0xffffffffu, p[e], off);
        // softmax
        float mx = p[0];
#pragma unroll
        for (int e = 1; e < 8; e++) mx = fmaxf(mx, p[e]);
        float s = 0.f;
#pragma unroll
        for (int e = 0; e < 8; e++) { p[e] = __expf(p[e] - mx); s += p[e]; }
        float inv = 1.f / s;
#pragma unroll
        for (int e = 0; e < 8; e++) p[e] *= inv;
        // top-2 (ties -> lowest index, matching lax.top_k)
        int i1 = 0; float v1 = p[0];
#pragma unroll
        for (int e = 1; e < 8; e++) if (p[e] > v1) { v1 = p[e]; i1 = e; }
        int i2 = -1; float v2 = -1e30f;
#pragma unroll
        for (int e = 0; e < 8; e++) if (e != i1 && p[e] > v2) { v2 = p[e]; i2 = e; }
#pragma unroll
        for (int e = 0; e < 8; e++) lsum[e] += p[e];

        if (lane == 0) {
            int hh = n & 3;
            atomicAdd(&scnt1[i1], 1);
            int r1 = atomicAdd(&srank[i1 * 4 + hh], 1);
            int r2 = atomicAdd(&srank[i2 * 4 + hh], 1);
            float wsum = v1 + v2;
            g_topi[2 * n]     = i1;  g_topi[2 * n + 1] = i2;
            g_topw[2 * n]     = v1 / wsum;
            g_topw[2 * n + 1] = v2 / wsum;
            g_srank[2 * n]     = r1;
            g_srank[2 * n + 1] = r2;
        }
    }
    if (lane == 0)
#pragma unroll
        for (int e = 0; e < 8; e++) atomicAdd(&ssum[e], lsum[e]);
    __syncthreads();
    if (tid < NBIN) g_blkcnt[blockIdx.x * NBIN + tid] = srank[tid];
    if (tid < Ee) {
        atomicAdd(&g_sump[tid], ssum[tid]);
        atomicAdd(&g_cnt1[tid], scnt1[tid]);
    }
}

// ---------------- phase2: prefix sums, offsets, tile map, aux loss ----------------
__global__ void k_phase2() {
    const int tid = threadIdx.x;
    if (tid < NBIN) {
        int base = 0;
        for (int b = 0; b < NGB; b++) {
            int c = g_blkcnt[b * NBIN + tid];
            g_blkbase[b * NBIN + tid] = base;
            base += c;
        }
        g_count[tid] = base;
    }
    __syncthreads();
    if (tid == 0) {
        int off = 0, toff = 0;
        for (int bin = 0; bin < NBIN; bin++) {
            g_off[bin] = off; g_tileoff[bin] = toff;
            off  += g_count[bin];
            toff += (g_count[bin] + 127) >> 7;
        }
        g_off[NBIN] = off; g_tileoff[NBIN] = toff;
        float aux = 0.f;
        for (int e = 0; e < Ee; e++)
            aux += (float)g_cnt1[e] * g_sump[e];
        g_aux = (float)Ee * aux / ((float)Nn * (float)Nn);
    }
}

// ---------------- scatter slots into bin-sorted list ----------------
__global__ void k_scatter() {
    int idx = blockIdx.x * blockDim.x + threadIdx.x;
    if (idx >= NSLOT) return;
    int n = idx >> 1;
    int bin = g_topi[idx] * 4 + (n & 3);
    int pos = g_off[bin] + g_blkbase[(n >> 7) * NBIN + bin] + g_srank[idx];
    g_perm[pos] = idx;
}

// ---------------- fused expert: gather x -> GEMM1(folded)+ReLU -> dot(v) -> scalar
// one CTA = 128 slots of one (e,h) bin. 256 threads, 8x8 micro.
__global__ void __launch_bounds__(256, 2)
k_expert(const float* __restrict__ x) {
    extern __shared__ float sm[];
    float* Xs   = sm;                       // 128 x 132
    float* Ms   = sm + 16896;               // 64 x 128 (k-chunk of folded M)
    float* vS   = sm + 25088;               // 128
    float* bS   = sm + 25216;               // 128
    float* sW   = sm + 25344;               // 128
    int*   sEnc = (int*)(sm + 25472);       // 128
    const int tid = threadIdx.x;

    const int t = blockIdx.x;
    if (t >= g_tileoff[NBIN]) return;
    int bin = 0;
#pragma unroll
    for (int i = 0; i < NBIN - 1; i++)
        if (t >= g_tileoff[i + 1]) bin++;
    const int tile = t - g_tileoff[bin];
    const int i0 = tile << 7;
    const int nvalid = min(128, g_count[bin] - i0);

    if (tid < 128) {
        int j = g_off[bin] + i0 + tid;
        if (j > NSLOT - 1) j = NSLOT - 1;   // tail rows: safe garbage, never stored
        int enc = g_perm[j];
        sEnc[tid] = enc;
        sW[tid]   = g_topw[enc];
        vS[tid]   = g_v [bin * 128 + tid];
        bS[tid]   = g_bM[bin * 128 + tid];
    }
    __syncthreads();

    // gather x rows (b = enc >> 3)
    for (int i = tid; i < 128 * 32; i += 256) {
        int r = i >> 5, c = (i & 31) << 2;
        *(float4*)(Xs + r * 132 + c) =
            *(const float4*)(x + (size_t)(sEnc[r] >> 3) * 128 + c);
    }

    const int tx = tid & 15, ty = tid >> 4;
    float acc[8][8];
#pragma unroll
    for (int i = 0; i < 8; i++)
#pragma unroll
        for (int j = 0; j < 8; j++) acc[i][j] = 0.f;

    const float* Me = g_M + (size_t)bin * 16384;
#pragma unroll
    for (int kc = 0; kc < 2; kc++) {
        for (int i = tid; i < 64 * 32; i += 256) {
            int r = i >> 5, c = (i & 31) << 2;
            *(float4*)(Ms + r * 128 + c) =
                *(const float4*)(Me + (size_t)(kc * 64 + r) * 128 + c);
        }
        __syncthreads();
#pragma unroll 8
        for (int kk = 0; kk < 64; kk++) {
            float4 b0 = *(const float4*)(Ms + kk * 128 + tx * 8);
            float4 b1v = *(const float4*)(Ms + kk * 128 + tx * 8 + 4);
            int k = kc * 64 + kk;
#pragma unroll
            for (int i = 0; i < 8; i++) {
                float a = Xs[(ty + 16 * i) * 132 + k];
                acc[i][0] = fmaf(a, b0.x, acc[i][0]);
                acc[i][1] = fmaf(a, b0.y, acc[i][1]);
                acc[i][2] = fmaf(a, b0.z, acc[i][2]);
                acc[i][3] = fmaf(a, b0.w, acc[i][3]);
                acc[i][4] = fmaf(a, b1v.x, acc[i][4]);
                acc[i][5] = fmaf(a, b1v.y, acc[i][5]);
                acc[i][6] = fmaf(a, b1v.z, acc[i][6]);
                acc[i][7] = fmaf(a, b1v.w, acc[i][7]);
            }
        }
        __syncthreads();
    }

    // epilogue: relu + bias, dot with v, reduce over 16 tx lanes, weighted store
    float bb[8], vv[8];
#pragma unroll
    for (int j = 0; j < 8; j++) {
        bb[j] = bS[tx * 8 + j];
        vv[j] = vS[tx * 8 + j];
    }
    float dot[8];
#pragma unroll
    for (int i = 0; i < 8; i++) {
        float d = 0.f;
#pragma unroll
        for (int j = 0; j < 8; j++)
            d = fmaf(fmaxf(acc[i][j] + bb[j], 0.f), vv[j], d);
        dot[i] = d;
    }
#pragma unroll
    for (int off = 8; off; off >>= 1)
#pragma unroll
        for (int i = 0; i < 8; i++)
            dot[i] += __shfl_xor_sync(0xffffffffu, dot[i], off);
    if (tx == 0) {
        float ceh = g_c[bin];
#pragma unroll
        for (int i = 0; i < 8; i++) {
            int r = ty + 16 * i;
            if (r < nvalid)
                g_contrib[sEnc[r]] = sW[r] * (dot[i] + ceh);
        }
    }
}

// ---------------- final: out[b] = bout + sum of 8 slot contributions ----------------
__global__ void k_final(const float* __restrict__ bout, float* __restrict__ out,
                        int out_size) {
    int b = blockIdx.x * blockDim.x + threadIdx.x;
    float4 c0 = *(const float4*)(g_contrib + (size_t)b * 8);
    float4 c1 = *(const float4*)(g_contrib + (size_t)b * 8 + 4);
    out[b] = bout[0] + ((c0.x + c0.y) + (c0.z + c0.w)) +
                       ((c1.x + c1.y) + (c1.z + c1.w));
    if (b == 0)
        for (int i = Bq; i < out_size; i++) out[i] = g_aux;   // aux loss scalar
}

// ---------------- launch ----------------
extern "C" void kernel_launch(void* const* d_in, const int* in_sizes, int n_in,
                              void* d_out, int out_size) {
    const float* x    = (const float*)d_in[0];
    const float* Wq   = (const float*)d_in[1];
    const float* bq   = (const float*)d_in[2];
    const float* Wk   = (const float*)d_in[3];
    const float* bk   = (const float*)d_in[4];
    const float* Wg   = (const float*)d_in[5];
    const float* W1   = (const float*)d_in[6];
    const float* b1   = (const float*)d_in[7];
    const float* W2   = (const float*)d_in[8];
    const float* b2   = (const float*)d_in[9];
    const float* Wout = (const float*)d_in[10];
    const float* bout = (const float*)d_in[11];
    float* out = (float*)d_out;

    const int smFold = (128 * 132 + 128 * 64) * 4;  // 100,352 B
    const int smProj = (128 * 132 + 64 * 128) * 4;  // 100,352 B
    const int smExp  = 25600 * 4;                   // 102,400 B
    cudaFuncSetAttribute(k_fold,   cudaFuncAttributeMaxDynamicSharedMemorySize, smFold);
    cudaFuncSetAttribute(k_proj,   cudaFuncAttributeMaxDynamicSharedMemorySize, smProj);
    cudaFuncSetAttribute(k_expert, cudaFuncAttributeMaxDynamicSharedMemorySize, smExp);

    void* pgate = nullptr;
    cudaGetSymbolAddress(&pgate, g_gate);

    k_init<<<1, 32>>>();
    k_fold<<<64, 256, smFold>>>(Wq, W1);
    k_fold_small<<<NBIN, 128>>>(bq, W1, b1, W2, b2, Wout);
    dim3 gp(4, 128);
    k_proj<<<gp, 256, smProj>>>(x, Wk, bk, (float*)pgate);
    k_gate<<<NGB, 256>>>(Wg);
    k_phase2<<<1, 64>>>();
    k_scatter<<<NSLOT / 256, 256>>>();
    k_expert<<<1056, 256, smExp>>>(x);
    k_final<<<Bq / 256, 256>>>(bout, out, out_size);
}

// round 7
// speedup vs baseline: 1.7089x; 1.1506x over previous
#include <cuda_runtime.h>

// Problem constants
#define Bq    16384
#define Dd    128
#define Hh    4
#define Ee    8
#define Nn    65536        // B*H tokens
#define OD    32           // ODIM = D/H
#define NSLOT 131072       // Nn * TOPK
#define NGB   128          // gating blocks = batches of 128 b's
#define NBIN  32           // (expert, head) bins

// ---------------- device scratch (no allocs allowed) ----------------
__device__ float g_M [NBIN * Dd * Dd];   // 2 MB  : folded Wq_h @ W1_e per (e,h)
__device__ float g_bM[NBIN * Dd];        // folded bias (bq_h @ W1_e + b1_e)
__device__ float g_v [NBIN * Dd];        // W2_e @ Wout_chunk_h
__device__ float g_c [NBIN];             // b2_e . Wout_chunk_h
__device__ float g_bg[NBIN];             // bk_h @ Wg contribution to logit (e,h)
__device__ int   g_topi [NSLOT];
__device__ float g_topw [NSLOT];
__device__ int   g_srank[NSLOT];         // rank within (b-block, bin)
__device__ int   g_blkcnt [NGB * NBIN];
__device__ int   g_blkbase[NGB * NBIN];  // per-bin exclusive prefix over blocks
__device__ int   g_off[NBIN + 1];
__device__ int   g_count[NBIN];
__device__ int   g_tileoff[NBIN + 1];
__device__ float g_sump[Ee];
__device__ int   g_cnt1[Ee];
__device__ float g_aux;
__device__ int   g_perm[NSLOT];          // bin-sorted list of (token*2+slot)
__device__ float g_contrib[NSLOT];       // per-slot weighted scalar contribution

// ---------------- init ----------------
__global__ void k_init() {
    int t = threadIdx.x;
    if (t < Ee) { g_sump[t] = 0.f; g_cnt1[t] = 0; }
}

// ---------------- fold: M[e*4+h] = Wq_h(128x128) @ W1_e(128x128) ----------------
// 64 blocks: (eh, half). 256 threads, 8x4 micro over a 128x64 output tile.
__global__ void k_fold(const float* __restrict__ Wq, const float* __restrict__ W1) {
    extern __shared__ float sm[];
    float* As = sm;               // 128 x 132 : Wq_h  (rows c, cols j)
    float* Bs = sm + 128 * 132;   // 128 x 64  : W1_e  (rows j, cols k-slice)
    const int tid = threadIdx.x;
    const int bb = blockIdx.x;
    const int eh = bb >> 1;
    const int e  = eh >> 2, h = eh & 3;
    const int n0 = (bb & 1) * 64;

    for (int i = tid; i < 128 * 32; i += 256) {
        int r = i >> 5, c = (i & 31) << 2;
        *(float4*)(As + r * 132 + c) = *(const float4*)(Wq + (size_t)r * 512 + h * 128 + c);
    }
    for (int i = tid; i < 128 * 16; i += 256) {
        int r = i >> 4, c = (i & 15) << 2;
        *(float4*)(Bs + r * 64 + c) =
            *(const float4*)(W1 + (size_t)e * 16384 + (size_t)r * 128 + n0 + c);
    }
    __syncthreads();

    const int tx = tid & 15, ty = tid >> 4;
    float acc[8][4];
#pragma unroll
    for (int i = 0; i < 8; i++)
#pragma unroll
        for (int j = 0; j < 4; j++) acc[i][j] = 0.f;

#pragma unroll 8
    for (int k = 0; k < 128; k++) {
        float4 b = *(const float4*)(Bs + k * 64 + tx * 4);
#pragma unroll
        for (int i = 0; i < 8; i++) {
            float a = As[(ty + 16 * i) * 132 + k];
            acc[i][0] = fmaf(a, b.x, acc[i][0]);
            acc[i][1] = fmaf(a, b.y, acc[i][1]);
            acc[i][2] = fmaf(a, b.z, acc[i][2]);
            acc[i][3] = fmaf(a, b.w, acc[i][3]);
        }
    }
#pragma unroll
    for (int i = 0; i < 8; i++) {
        int m = ty + 16 * i;
        *(float4*)(g_M + (size_t)eh * 16384 + (size_t)m * 128 + n0 + tx * 4) =
            *(float4*)acc[i];
    }
}

// ---------------- fold small: bM, v, c, bg per (e,h) ----------------
__global__ void k_fold_small(const float* __restrict__ bq, const float* __restrict__ W1,
                             const float* __restrict__ b1, const float* __restrict__ W2,
                             const float* __restrict__ b2, const float* __restrict__ Wout,
                             const float* __restrict__ bk, const float* __restrict__ Wg) {
    const int eh = blockIdx.x;
    const int e = eh >> 2, h = eh & 3;
    const int k = threadIdx.x;   // 0..127
    // bM[eh][k] = b1[e][k] + sum_j bq[h*128+j] * W1[e][j][k]
    float s = b1[e * 128 + k];
    for (int j = 0; j < 128; j++)
        s = fmaf(bq[h * 128 + j], W1[(size_t)e * 16384 + (size_t)j * 128 + k], s);
    g_bM[eh * 128 + k] = s;
    // v[eh][j] = sum_t W2[e][j][t] * Wout[h*32+t]   (NTASK = 1)
    float v = 0.f;
    for (int t = 0; t < 32; t++)
        v = fmaf(W2[(size_t)e * 4096 + (size_t)k * 32 + t], Wout[h * 32 + t], v);
    g_v[eh * 128 + k] = v;
    if (k == 0) {
        float c = 0.f;
        for (int t = 0; t < 32; t++)
            c = fmaf(b2[e * 32 + t], Wout[h * 32 + t], c);
        g_c[eh] = c;
    }
    if (k == 1) {
        // logit bias: sum_c bk[h*128+c] * Wg[c][e]
        float s2 = 0.f;
        for (int c = 0; c < 128; c++)
            s2 = fmaf(bk[h * 128 + c], Wg[c * 8 + e], s2);
        g_bg[eh] = s2;
    }
}

// ---------------- fused projection + gating -----------------------------------
// CTA (h, by): gate features for 128 tokens n=(by*128+b')*4+h computed in-tile,
// then softmax/top-2/routing done from smem. No gmem gate tensor at all.
__global__ void __launch_bounds__(256, 2)
k_projgate(const float* __restrict__ X, const float* __restrict__ Wk,
           const float* __restrict__ Wg) {
    extern __shared__ float sm[];
    float* As = sm;               // 128 x 132 : X tile, reused for C (gate feats)
    float* Bs = sm + 128 * 132;   // 64 x 128  : Wk k-chunk
    __shared__ int   srank[Ee];
    __shared__ float ssum [Ee];
    __shared__ int   scnt1[Ee];
    const int tid = threadIdx.x;
    const int h  = blockIdx.x;
    const int by = blockIdx.y;
    const int m0 = by * 128;
    const int n0 = h * 128;
    if (tid < Ee) { srank[tid] = 0; ssum[tid] = 0.f; scnt1[tid] = 0; }

    for (int i = tid; i < 128 * 32; i += 256) {
        int r = i >> 5, c = (i & 31) << 2;
        *(float4*)(As + r * 132 + c) = *(const float4*)(X + (size_t)(m0 + r) * Dd + c);
    }

    const int tx = tid & 15, ty = tid >> 4;
    float acc[8][8];
#pragma unroll
    for (int i = 0; i < 8; i++)
#pragma unroll
        for (int j = 0; j < 8; j++) acc[i][j] = 0.f;

#pragma unroll
    for (int kc = 0; kc < 2; kc++) {
        for (int i = tid; i < 64 * 32; i += 256) {
            int r = i >> 5, c = (i & 31) << 2;
            *(float4*)(Bs + r * 128 + c) =
                *(const float4*)(Wk + (size_t)(kc * 64 + r) * 512 + n0 + c);
        }
        __syncthreads();
#pragma unroll 8
        for (int kk = 0; kk < 64; kk++) {
            float4 b0 = *(const float4*)(Bs + kk * 128 + tx * 8);
            float4 b1v = *(const float4*)(Bs + kk * 128 + tx * 8 + 4);
            int k = kc * 64 + kk;
#pragma unroll
            for (int i = 0; i < 8; i++) {
                float a = As[(ty + 16 * i) * 132 + k];
                acc[i][0] = fmaf(a, b0.x, acc[i][0]);
                acc[i][1] = fmaf(a, b0.y, acc[i][1]);
                acc[i][2] = fmaf(a, b0.z, acc[i][2]);
                acc[i][3] = fmaf(a, b0.w, acc[i][3]);
                acc[i][4] = fmaf(a, b1v.x, acc[i][4]);
                acc[i][5] = fmaf(a, b1v.y, acc[i][5]);
                acc[i][6] = fmaf(a, b1v.z, acc[i][6]);
                acc[i][7] = fmaf(a, b1v.w, acc[i][7]);
            }
        }
        __syncthreads();
    }

    // stash gate features C[128][128] into As (token data no longer needed)
#pragma unroll
    for (int i = 0; i < 8; i++) {
        int m = ty + 16 * i;
        *(float4*)(As + m * 132 + tx * 8)     = *(float4*)&acc[i][0];
        *(float4*)(As + m * 132 + tx * 8 + 4) = *(float4*)&acc[i][4];
    }
    __syncthreads();

    // ---- gating epilogue: warp per token, 16 tokens per warp ----
    const int lane = tid & 31, warp = tid >> 5;
    float wr[4][8];
#pragma unroll
    for (int i = 0; i < 4; i++)
#pragma unroll
        for (int e = 0; e < 8; e++)
            wr[i][e] = Wg[(lane * 4 + i) * 8 + e];
    float blg[8];
#pragma unroll
    for (int e = 0; e < 8; e++) blg[e] = g_bg[e * 4 + h];

    float lsum[8];
#pragma unroll
    for (int e = 0; e < 8; e++) lsum[e] = 0.f;

    for (int it = 0; it < 16; it++) {
        int m = warp * 16 + it;
        float4 gv = *(const float4*)(As + m * 132 + lane * 4);
        float p[8];
#pragma unroll
        for (int e = 0; e < 8; e++)
            p[e] = gv.x * wr[0][e] + gv.y * wr[1][e] + gv.z * wr[2][e] + gv.w * wr[3][e];
#pragma unroll
        for (int off = 16; off; off >>= 1)
#pragma unroll
            for (int e = 0; e < 8; e++)
                p[e] += __shfl_xor_sync(0xffffffffu, p[e], off);
#pragma unroll
        for (int e = 0; e < 8; e++) p[e] += blg[e];
        // softmax
        float mx = p[0];
#pragma unroll
        for (int e = 1; e < 8; e++) mx = fmaxf(mx, p[e]);
        float s = 0.f;
#pragma unroll
        for (int e = 0; e < 8; e++) { p[e] = __expf(p[e] - mx); s += p[e]; }
        float inv = 1.f / s;
#pragma unroll
        for (int e = 0; e < 8; e++) p[e] *= inv;
        // top-2 (ties -> lowest index, matching lax.top_k)
        int i1 = 0; float v1 = p[0];
#pragma unroll
        for (int e = 1; e < 8; e++) if (p[e] > v1) { v1 = p[e]; i1 = e; }
        int i2 = -1; float v2 = -1e30f;
#pragma unroll
        for (int e = 0; e < 8; e++) if (e != i1 && p[e] > v2) { v2 = p[e]; i2 = e; }
#pragma unroll
        for (int e = 0; e < 8; e++) lsum[e] += p[e];

        if (lane == 0) {
            int n = (m0 + m) * 4 + h;
            atomicAdd(&scnt1[i1], 1);
            int r1 = atomicAdd(&srank[i1], 1);
            int r2 = atomicAdd(&srank[i2], 1);
            float wsum = v1 + v2;
            g_topi[2 * n]     = i1;  g_topi[2 * n + 1] = i2;
            g_topw[2 * n]     = v1 / wsum;
            g_topw[2 * n + 1] = v2 / wsum;
            g_srank[2 * n]     = r1;
            g_srank[2 * n + 1] = r2;
        }
    }
    if (lane == 0)
#pragma unroll
        for (int e = 0; e < 8; e++) atomicAdd(&ssum[e], lsum[e]);
    __syncthreads();
    if (tid < Ee) {
        g_blkcnt[by * NBIN + tid * 4 + h] = srank[tid];
        atomicAdd(&g_sump[tid], ssum[tid]);
        atomicAdd(&g_cnt1[tid], scnt1[tid]);
    }
}

// ---------------- phase2: prefix sums, offsets, tile map, aux loss ----------------
__global__ void k_phase2() {
    const int tid = threadIdx.x;
    if (tid < NBIN) {
        int base = 0;
        for (int b = 0; b < NGB; b++) {
            int c = g_blkcnt[b * NBIN + tid];
            g_blkbase[b * NBIN + tid] = base;
            base += c;
        }
        g_count[tid] = base;
    }
    __syncthreads();
    if (tid == 0) {
        int off = 0, toff = 0;
        for (int bin = 0; bin < NBIN; bin++) {
            g_off[bin] = off; g_tileoff[bin] = toff;
            off  += g_count[bin];
            toff += (g_count[bin] + 127) >> 7;
        }
        g_off[NBIN] = off; g_tileoff[NBIN] = toff;
        float aux = 0.f;
        for (int e = 0; e < Ee; e++)
            aux += (float)g_cnt1[e] * g_sump[e];
        g_aux = (float)Ee * aux / ((float)Nn * (float)Nn);
    }
}

// ---------------- scatter slots into bin-sorted list ----------------
__global__ void k_scatter() {
    int idx = blockIdx.x * blockDim.x + threadIdx.x;
    if (idx >= NSLOT) return;
    int n = idx >> 1;
    int bin = g_topi[idx] * 4 + (n & 3);
    int gb  = idx >> 10;                 // b>>7 where b = n>>2
    int pos = g_off[bin] + g_blkbase[gb * NBIN + bin] + g_srank[idx];
    g_perm[pos] = idx;
}

// ---------------- fused expert: gather x -> GEMM1(folded)+ReLU -> dot(v) -> scalar
// one CTA = 128 slots of one (e,h) bin. 256 threads, 8x8 micro.
__global__ void __launch_bounds__(256, 2)
k_expert(const float* __restrict__ x) {
    extern __shared__ float sm[];
    float* Xs   = sm;                       // 128 x 132
    float* Ms   = sm + 16896;               // 64 x 128 (k-chunk of folded M)
    float* vS   = sm + 25088;               // 128
    float* bS   = sm + 25216;               // 128
    float* sW   = sm + 25344;               // 128
    int*   sEnc = (int*)(sm + 25472);       // 128
    const int tid = threadIdx.x;

    const int t = blockIdx.x;
    if (t >= g_tileoff[NBIN]) return;
    int bin = 0;
#pragma unroll
    for (int i = 0; i < NBIN - 1; i++)
        if (t >= g_tileoff[i + 1]) bin++;
    const int tile = t - g_tileoff[bin];
    const int i0 = tile << 7;
    const int nvalid = min(128, g_count[bin] - i0);

    if (tid < 128) {
        int j = g_off[bin] + i0 + tid;
        if (j > NSLOT - 1) j = NSLOT - 1;   // tail rows: safe garbage, never stored
        int enc = g_perm[j];
        sEnc[tid] = enc;
        sW[tid]   = g_topw[enc];
        vS[tid]   = g_v [bin * 128 + tid];
        bS[tid]   = g_bM[bin * 128 + tid];
    }
    __syncthreads();

    // gather x rows (b = enc >> 3)
    for (int i = tid; i < 128 * 32; i += 256) {
        int r = i >> 5, c = (i & 31) << 2;
        *(float4*)(Xs + r * 132 + c) =
            *(const float4*)(x + (size_t)(sEnc[r] >> 3) * 128 + c);
    }

    const int tx = tid & 15, ty = tid >> 4;
    float acc[8][8];
#pragma unroll
    for (int i = 0; i < 8; i++)
#pragma unroll
        for (int j = 0; j < 8; j++) acc[i][j] = 0.f;

    const float* Me = g_M + (size_t)bin * 16384;
#pragma unroll
    for (int kc = 0; kc < 2; kc++) {
        for (int i = tid; i < 64 * 32; i += 256) {
            int r = i >> 5, c = (i & 31) << 2;
            *(float4*)(Ms + r * 128 + c) =
                *(const float4*)(Me + (size_t)(kc * 64 + r) * 128 + c);
        }
        __syncthreads();
#pragma unroll 8
        for (int kk = 0; kk < 64; kk++) {
            float4 b0 = *(const float4*)(Ms + kk * 128 + tx * 8);
            float4 b1v = *(const float4*)(Ms + kk * 128 + tx * 8 + 4);
            int k = kc * 64 + kk;
#pragma unroll
            for (int i = 0; i < 8; i++) {
                float a = Xs[(ty + 16 * i) * 132 + k];
                acc[i][0] = fmaf(a, b0.x, acc[i][0]);
                acc[i][1] = fmaf(a, b0.y, acc[i][1]);
                acc[i][2] = fmaf(a, b0.z, acc[i][2]);
                acc[i][3] = fmaf(a, b0.w, acc[i][3]);
                acc[i][4] = fmaf(a, b1v.x, acc[i][4]);
                acc[i][5] = fmaf(a, b1v.y, acc[i][5]);
                acc[i][6] = fmaf(a, b1v.z, acc[i][6]);
                acc[i][7] = fmaf(a, b1v.w, acc[i][7]);
            }
        }
        __syncthreads();
    }

    // epilogue: relu + bias, dot with v, reduce over 16 tx lanes, weighted store
    float bb[8], vv[8];
#pragma unroll
    for (int j = 0; j < 8; j++) {
        bb[j] = bS[tx * 8 + j];
        vv[j] = vS[tx * 8 + j];
    }
    float dot[8];
#pragma unroll
    for (int i = 0; i < 8; i++) {
        float d = 0.f;
#pragma unroll
        for (int j = 0; j < 8; j++)
            d = fmaf(fmaxf(acc[i][j] + bb[j], 0.f), vv[j], d);
        dot[i] = d;
    }
#pragma unroll
    for (int off = 8; off; off >>= 1)
#pragma unroll
        for (int i = 0; i < 8; i++)
            dot[i] += __shfl_xor_sync(0xffffffffu, dot[i], off);
    if (tx == 0) {
        float ceh = g_c[bin];
#pragma unroll
        for (int i = 0; i < 8; i++) {
            int r = ty + 16 * i;
            if (r < nvalid)
                g_contrib[sEnc[r]] = sW[r] * (dot[i] + ceh);
        }
    }
}

// ---------------- final: out[b] = bout + sum of 8 slot contributions ----------------
__global__ void k_final(const float* __restrict__ bout, float* __restrict__ out,
                        int out_size) {
    int b = blockIdx.x * blockDim.x + threadIdx.x;
    float4 c0 = *(const float4*)(g_contrib + (size_t)b * 8);
    float4 c1 = *(const float4*)(g_contrib + (size_t)b * 8 + 4);
    out[b] = bout[0] + ((c0.x + c0.y) + (c0.z + c0.w)) +
                       ((c1.x + c1.y) + (c1.z + c1.w));
    if (b == 0)
        for (int i = Bq; i < out_size; i++) out[i] = g_aux;   // aux loss scalar
}

// ---------------- launch ----------------
extern "C" void kernel_launch(void* const* d_in, const int* in_sizes, int n_in,
                              void* d_out, int out_size) {
    const float* x    = (const float*)d_in[0];
    const float* Wq   = (const float*)d_in[1];
    const float* bq   = (const float*)d_in[2];
    const float* Wk   = (const float*)d_in[3];
    const float* bk   = (const float*)d_in[4];
    const float* Wg   = (const float*)d_in[5];
    const float* W1   = (const float*)d_in[6];
    const float* b1   = (const float*)d_in[7];
    const float* W2   = (const float*)d_in[8];
    const float* b2   = (const float*)d_in[9];
    const float* Wout = (const float*)d_in[10];
    const float* bout = (const float*)d_in[11];
    float* out = (float*)d_out;

    const int smFold = (128 * 132 + 128 * 64) * 4;  // 100,352 B
    const int smProj = (128 * 132 + 64 * 128) * 4;  // 100,352 B
    const int smExp  = 25600 * 4;                   // 102,400 B
    cudaFuncSetAttribute(k_fold,     cudaFuncAttributeMaxDynamicSharedMemorySize, smFold);
    cudaFuncSetAttribute(k_projgate, cudaFuncAttributeMaxDynamicSharedMemorySize, smProj);
    cudaFuncSetAttribute(k_expert,   cudaFuncAttributeMaxDynamicSharedMemorySize, smExp);

    k_init<<<1, 32>>>();
    k_fold<<<64, 256, smFold>>>(Wq, W1);
    k_fold_small<<<NBIN, 128>>>(bq, W1, b1, W2, b2, Wout, bk, Wg);
    dim3 gp(4, 128);
    k_projgate<<<gp, 256, smProj>>>(x, Wk, Wg);
    k_phase2<<<1, 64>>>();
    k_scatter<<<NSLOT / 256, 256>>>();
    k_expert<<<1056, 256, smExp>>>(x);
    k_final<<<Bq / 256, 256>>>(bout, out, out_size);
}

// round 8
// speedup vs baseline: 1.7939x; 1.0497x over previous
#include <cuda_runtime.h>

// Problem constants
#define Bq    16384
#define Dd    128
#define Hh    4
#define Ee    8
#define Nn    65536        // B*H tokens
#define OD    32           // ODIM = D/H
#define NSLOT 131072       // Nn * TOPK
#define NGB   128          // gating blocks = batches of 128 b's
#define NBIN  32           // (expert, head) bins

typedef unsigned long long ull;

// packed f32x2 FMA: each lane of the 64-bit pack is an independent FMA chain,
// so per-output accumulation order is IDENTICAL to the scalar version.
#define FMA2(acc, a2, b2) \
    asm("fma.rn.f32x2 %0, %1, %2, %0;" : "+l"(acc) : "l"(a2), "l"(b2))
#define PACKBC(d, s) \
    asm("mov.b64 %0, {%1, %1};" : "=l"(d) : "f"(s))
#define UNPACK2(lo, hi, p) \
    asm("mov.b64 {%0, %1}, %2;" : "=f"(lo), "=f"(hi) : "l"(p))

// ---------------- device scratch (no allocs allowed) ----------------
__device__ float g_M [NBIN * Dd * Dd];   // 2 MB  : folded Wq_h @ W1_e per (e,h)
__device__ float g_bM[NBIN * Dd];        // folded bias (bq_h @ W1_e + b1_e)
__device__ float g_v [NBIN * Dd];        // W2_e @ Wout_chunk_h
__device__ float g_c [NBIN];             // b2_e . Wout_chunk_h
__device__ float g_bg[NBIN];             // bk_h @ Wg contribution to logit (e,h)
__device__ int   g_topi [NSLOT];
__device__ float g_topw [NSLOT];
__device__ int   g_srank[NSLOT];         // rank within (b-block, bin)
__device__ int   g_blkcnt [NGB * NBIN];
__device__ int   g_blkbase[NGB * NBIN];  // per-bin exclusive prefix over blocks
__device__ int   g_off[NBIN + 1];
__device__ int   g_count[NBIN];
__device__ int   g_tileoff[NBIN + 1];
__device__ float g_sump[Ee];
__device__ int   g_cnt1[Ee];
__device__ float g_aux;
__device__ int   g_perm[NSLOT];          // bin-sorted list of (token*2+slot)
__device__ float g_contrib[NSLOT];       // per-slot weighted scalar contribution

// ---------------- init ----------------
__global__ void k_init() {
    int t = threadIdx.x;
    if (t < Ee) { g_sump[t] = 0.f; g_cnt1[t] = 0; }
}

// ---------------- fold: M[e*4+h] = Wq_h(128x128) @ W1_e(128x128) ----------------
// 64 blocks: (eh, half). 256 threads, 8x4 micro over a 128x64 output tile.
__global__ void k_fold(const float* __restrict__ Wq, const float* __restrict__ W1) {
    extern __shared__ float sm[];
    float* As = sm;               // 128 x 132 : Wq_h  (rows c, cols j)
    float* Bs = sm + 128 * 132;   // 128 x 64  : W1_e  (rows j, cols k-slice)
    const int tid = threadIdx.x;
    const int bb = blockIdx.x;
    const int eh = bb >> 1;
    const int e  = eh >> 2, h = eh & 3;
    const int n0 = (bb & 1) * 64;

    for (int i = tid; i < 128 * 32; i += 256) {
        int r = i >> 5, c = (i & 31) << 2;
        *(float4*)(As + r * 132 + c) = *(const float4*)(Wq + (size_t)r * 512 + h * 128 + c);
    }
    for (int i = tid; i < 128 * 16; i += 256) {
        int r = i >> 4, c = (i & 15) << 2;
        *(float4*)(Bs + r * 64 + c) =
            *(const float4*)(W1 + (size_t)e * 16384 + (size_t)r * 128 + n0 + c);
    }
    __syncthreads();

    const int tx = tid & 15, ty = tid >> 4;
    float acc[8][4];
#pragma unroll
    for (int i = 0; i < 8; i++)
#pragma unroll
        for (int j = 0; j < 4; j++) acc[i][j] = 0.f;

#pragma unroll 8
    for (int k = 0; k < 128; k++) {
        float4 b = *(const float4*)(Bs + k * 64 + tx * 4);
#pragma unroll
        for (int i = 0; i < 8; i++) {
            float a = As[(ty + 16 * i) * 132 + k];
            acc[i][0] = fmaf(a, b.x, acc[i][0]);
            acc[i][1] = fmaf(a, b.y, acc[i][1]);
            acc[i][2] = fmaf(a, b.z, acc[i][2]);
            acc[i][3] = fmaf(a, b.w, acc[i][3]);
        }
    }
#pragma unroll
    for (int i = 0; i < 8; i++) {
        int m = ty + 16 * i;
        *(float4*)(g_M + (size_t)eh * 16384 + (size_t)m * 128 + n0 + tx * 4) =
            *(float4*)acc[i];
    }
}

// ---------------- fold small: bM, v, c, bg per (e,h) ----------------
__global__ void k_fold_small(const float* __restrict__ bq, const float* __restrict__ W1,
                             const float* __restrict__ b1, const float* __restrict__ W2,
                             const float* __restrict__ b2, const float* __restrict__ Wout,
                             const float* __restrict__ bk, const float* __restrict__ Wg) {
    const int eh = blockIdx.x;
    const int e = eh >> 2, h = eh & 3;
    const int k = threadIdx.x;   // 0..127
    // bM[eh][k] = b1[e][k] + sum_j bq[h*128+j] * W1[e][j][k]
    float s = b1[e * 128 + k];
    for (int j = 0; j < 128; j++)
        s = fmaf(bq[h * 128 + j], W1[(size_t)e * 16384 + (size_t)j * 128 + k], s);
    g_bM[eh * 128 + k] = s;
    // v[eh][j] = sum_t W2[e][j][t] * Wout[h*32+t]   (NTASK = 1)
    float v = 0.f;
    for (int t = 0; t < 32; t++)
        v = fmaf(W2[(size_t)e * 4096 + (size_t)k * 32 + t], Wout[h * 32 + t], v);
    g_v[eh * 128 + k] = v;
    if (k == 0) {
        float c = 0.f;
        for (int t = 0; t < 32; t++)
            c = fmaf(b2[e * 32 + t], Wout[h * 32 + t], c);
        g_c[eh] = c;
    }
    if (k == 1) {
        // logit bias: sum_c bk[h*128+c] * Wg[c][e]
        float s2 = 0.f;
        for (int c = 0; c < 128; c++)
            s2 = fmaf(bk[h * 128 + c], Wg[c * 8 + e], s2);
        g_bg[eh] = s2;
    }
}

// ---------------- fused projection + gating -----------------------------------
// CTA (h, by): gate features for 128 tokens n=(by*128+b')*4+h computed in-tile,
// then softmax/top-2/routing done from smem. Mainloop uses packed fma.rn.f32x2.
__global__ void __launch_bounds__(256, 2)
k_projgate(const float* __restrict__ X, const float* __restrict__ Wk,
           const float* __restrict__ Wg) {
    extern __shared__ float sm[];
    float* As = sm;               // 128 x 132 : X tile, reused for C (gate feats)
    float* Bs = sm + 128 * 132;   // 64 x 128  : Wk k-chunk
    __shared__ int   srank[Ee];
    __shared__ float ssum [Ee];
    __shared__ int   scnt1[Ee];
    const int tid = threadIdx.x;
    const int h  = blockIdx.x;
    const int by = blockIdx.y;
    const int m0 = by * 128;
    const int n0 = h * 128;
    if (tid < Ee) { srank[tid] = 0; ssum[tid] = 0.f; scnt1[tid] = 0; }

    for (int i = tid; i < 128 * 32; i += 256) {
        int r = i >> 5, c = (i & 31) << 2;
        *(float4*)(As + r * 132 + c) = *(const float4*)(X + (size_t)(m0 + r) * Dd + c);
    }

    const int tx = tid & 15, ty = tid >> 4;
    ull acc2[8][4];                 // packed pairs along n: (c[n], c[n+1])
#pragma unroll
    for (int i = 0; i < 8; i++)
#pragma unroll
        for (int j = 0; j < 4; j++) acc2[i][j] = 0ull;

#pragma unroll
    for (int kc = 0; kc < 2; kc++) {
        for (int i = tid; i < 64 * 32; i += 256) {
            int r = i >> 5, c = (i & 31) << 2;
            *(float4*)(Bs + r * 128 + c) =
                *(const float4*)(Wk + (size_t)(kc * 64 + r) * 512 + n0 + c);
        }
        __syncthreads();
#pragma unroll 8
        for (int kk = 0; kk < 64; kk++) {
            ulonglong2 bp0 = *(const ulonglong2*)(Bs + kk * 128 + tx * 8);
            ulonglong2 bp1 = *(const ulonglong2*)(Bs + kk * 128 + tx * 8 + 4);
            int k = kc * 64 + kk;
#pragma unroll
            for (int i = 0; i < 8; i++) {
                float a = As[(ty + 16 * i) * 132 + k];
                ull ap; PACKBC(ap, a);
                FMA2(acc2[i][0], ap, bp0.x);
                FMA2(acc2[i][1], ap, bp0.y);
                FMA2(acc2[i][2], ap, bp1.x);
                FMA2(acc2[i][3], ap, bp1.y);
            }
        }
        __syncthreads();
    }

    // stash gate features C[128][128] into As (token data no longer needed)
#pragma unroll
    for (int i = 0; i < 8; i++) {
        int m = ty + 16 * i;
#pragma unroll
        for (int j = 0; j < 4; j++)
            *(ull*)(As + m * 132 + tx * 8 + 2 * j) = acc2[i][j];
    }
    __syncthreads();

    // ---- gating epilogue: warp per token, 16 tokens per warp ----
    const int lane = tid & 31, warp = tid >> 5;
    float wr[4][8];
#pragma unroll
    for (int i = 0; i < 4; i++)
#pragma unroll
        for (int e = 0; e < 8; e++)
            wr[i][e] = Wg[(lane * 4 + i) * 8 + e];
    float blg[8];
#pragma unroll
    for (int e = 0; e < 8; e++) blg[e] = g_bg[e * 4 + h];

    float lsum[8];
#pragma unroll
    for (int e = 0; e < 8; e++) lsum[e] = 0.f;

    for (int it = 0; it < 16; it++) {
        int m = warp * 16 + it;
        float4 gv = *(const float4*)(As + m * 132 + lane * 4);
        float p[8];
#pragma unroll
        for (int e = 0; e < 8; e++)
            p[e] = gv.x * wr[0][e] + gv.y * wr[1][e] + gv.z * wr[2][e] + gv.w * wr[3][e];
#pragma unroll
        for (int off = 16; off; off >>= 1)
#pragma unroll
            for (int e = 0; e < 8; e++)
                p[e] += __shfl_xor_sync(0xffffffffu, p[e], off);
#pragma unroll
        for (int e = 0; e < 8; e++) p[e] += blg[e];
        // softmax
        float mx = p[0];
#pragma unroll
        for (int e = 1; e < 8; e++) mx = fmaxf(mx, p[e]);
        float s = 0.f;
#pragma unroll
        for (int e = 0; e < 8; e++) { p[e] = __expf(p[e] - mx); s += p[e]; }
        float inv = 1.f / s;
#pragma unroll
        for (int e = 0; e < 8; e++) p[e] *= inv;
        // top-2 (ties -> lowest index, matching lax.top_k)
        int i1 = 0; float v1 = p[0];
#pragma unroll
        for (int e = 1; e < 8; e++) if (p[e] > v1) { v1 = p[e]; i1 = e; }
        int i2 = -1; float v2 = -1e30f;
#pragma unroll
        for (int e = 0; e < 8; e++) if (e != i1 && p[e] > v2) { v2 = p[e]; i2 = e; }
#pragma unroll
        for (int e = 0; e < 8; e++) lsum[e] += p[e];

        if (lane == 0) {
            int n = (m0 + m) * 4 + h;
            atomicAdd(&scnt1[i1], 1);
            int r1 = atomicAdd(&srank[i1], 1);
            int r2 = atomicAdd(&srank[i2], 1);
            float wsum = v1 + v2;
            g_topi[2 * n]     = i1;  g_topi[2 * n + 1] = i2;
            g_topw[2 * n]     = v1 / wsum;
            g_topw[2 * n + 1] = v2 / wsum;
            g_srank[2 * n]     = r1;
            g_srank[2 * n + 1] = r2;
        }
    }
    if (lane == 0)
#pragma unroll
        for (int e = 0; e < 8; e++) atomicAdd(&ssum[e], lsum[e]);
    __syncthreads();
    if (tid < Ee) {
        g_blkcnt[by * NBIN + tid * 4 + h] = srank[tid];
        atomicAdd(&g_sump[tid], ssum[tid]);
        atomicAdd(&g_cnt1[tid], scnt1[tid]);
    }
}

// ---------------- phase2: prefix sums, offsets, tile map, aux loss ----------------
__global__ void k_phase2() {
    const int tid = threadIdx.x;
    if (tid < NBIN) {
        int base = 0;
        for (int b = 0; b < NGB; b++) {
            int c = g_blkcnt[b * NBIN + tid];
            g_blkbase[b * NBIN + tid] = base;
            base += c;
        }
        g_count[tid] = base;
    }
    __syncthreads();
    if (tid == 0) {
        int off = 0, toff = 0;
        for (int bin = 0; bin < NBIN; bin++) {
            g_off[bin] = off; g_tileoff[bin] = toff;
            off  += g_count[bin];
            toff += (g_count[bin] + 127) >> 7;
        }
        g_off[NBIN] = off; g_tileoff[NBIN] = toff;
        float aux = 0.f;
        for (int e = 0; e < Ee; e++)
            aux += (float)g_cnt1[e] * g_sump[e];
        g_aux = (float)Ee * aux / ((float)Nn * (float)Nn);
    }
}

// ---------------- scatter slots into bin-sorted list ----------------
__global__ void k_scatter() {
    int idx = blockIdx.x * blockDim.x + threadIdx.x;
    if (idx >= NSLOT) return;
    int n = idx >> 1;
    int bin = g_topi[idx] * 4 + (n & 3);
    int gb  = idx >> 10;                 // b>>7 where b = n>>2
    int pos = g_off[bin] + g_blkbase[gb * NBIN + bin] + g_srank[idx];
    g_perm[pos] = idx;
}

// ---------------- fused expert: gather x -> GEMM1(folded)+ReLU -> dot(v) -> scalar
// one CTA = 128 slots of one (e,h) bin. 256 threads, 8x8 micro, packed fma.f32x2.
__global__ void __launch_bounds__(256, 2)
k_expert(const float* __restrict__ x) {
    extern __shared__ float sm[];
    float* Xs   = sm;                       // 128 x 132
    float* Ms   = sm + 16896;               // 64 x 128 (k-chunk of folded M)
    float* vS   = sm + 25088;               // 128
    float* bS   = sm + 25216;               // 128
    float* sW   = sm + 25344;               // 128
    int*   sEnc = (int*)(sm + 25472);       // 128
    const int tid = threadIdx.x;

    const int t = blockIdx.x;
    if (t >= g_tileoff[NBIN]) return;
    int bin = 0;
#pragma unroll
    for (int i = 0; i < NBIN - 1; i++)
        if (t >= g_tileoff[i + 1]) bin++;
    const int tile = t - g_tileoff[bin];
    const int i0 = tile << 7;
    const int nvalid = min(128, g_count[bin] - i0);

    if (tid < 128) {
        int j = g_off[bin] + i0 + tid;
        if (j > NSLOT - 1) j = NSLOT - 1;   // tail rows: safe garbage, never stored
        int enc = g_perm[j];
        sEnc[tid] = enc;
        sW[tid]   = g_topw[enc];
        vS[tid]   = g_v [bin * 128 + tid];
        bS[tid]   = g_bM[bin * 128 + tid];
    }
    __syncthreads();

    // gather x rows (b = enc >> 3)
    for (int i = tid; i < 128 * 32; i += 256) {
        int r = i >> 5, c = (i & 31) << 2;
        *(float4*)(Xs + r * 132 + c) =
            *(const float4*)(x + (size_t)(sEnc[r] >> 3) * 128 + c);
    }

    const int tx = tid & 15, ty = tid >> 4;
    ull acc2[8][4];                 // packed pairs along n
#pragma unroll
    for (int i = 0; i < 8; i++)
#pragma unroll
        for (int j = 0; j < 4; j++) acc2[i][j] = 0ull;

    const float* Me = g_M + (size_t)bin * 16384;
#pragma unroll
    for (int kc = 0; kc < 2; kc++) {
        for (int i = tid; i < 64 * 32; i += 256) {
            int r = i >> 5, c = (i & 31) << 2;
            *(float4*)(Ms + r * 128 + c) =
                *(const float4*)(Me + (size_t)(kc * 64 + r) * 128 + c);
        }
        __syncthreads();
#pragma unroll 8
        for (int kk = 0; kk < 64; kk++) {
            ulonglong2 bp0 = *(const ulonglong2*)(Ms + kk * 128 + tx * 8);
            ulonglong2 bp1 = *(const ulonglong2*)(Ms + kk * 128 + tx * 8 + 4);
            int k = kc * 64 + kk;
#pragma unroll
            for (int i = 0; i < 8; i++) {
                float a = Xs[(ty + 16 * i) * 132 + k];
                ull ap; PACKBC(ap, a);
                FMA2(acc2[i][0], ap, bp0.x);
                FMA2(acc2[i][1], ap, bp0.y);
                FMA2(acc2[i][2], ap, bp1.x);
                FMA2(acc2[i][3], ap, bp1.y);
            }
        }
        __syncthreads();
    }

    // epilogue: unpack, relu + bias, dot with v, reduce over 16 tx lanes, store
    float bb[8], vv[8];
#pragma unroll
    for (int j = 0; j < 8; j++) {
        bb[j] = bS[tx * 8 + j];
        vv[j] = vS[tx * 8 + j];
    }
    float dot[8];
#pragma unroll
    for (int i = 0; i < 8; i++) {
        float c[8];
#pragma unroll
        for (int j = 0; j < 4; j++)
            UNPACK2(c[2 * j], c[2 * j + 1], acc2[i][j]);
        float d = 0.f;
#pragma unroll
        for (int j = 0; j < 8; j++)
            d = fmaf(fmaxf(c[j] + bb[j], 0.f), vv[j], d);
        dot[i] = d;
    }
#pragma unroll
    for (int off = 8; off; off >>= 1)
#pragma unroll
        for (int i = 0; i < 8; i++)
            dot[i] += __shfl_xor_sync(0xffffffffu, dot[i], off);
    if (tx == 0) {
        float ceh = g_c[bin];
#pragma unroll
        for (int i = 0; i < 8; i++) {
            int r = ty + 16 * i;
            if (r < nvalid)
                g_contrib[sEnc[r]] = sW[r] * (dot[i] + ceh);
        }
    }
}

// ---------------- final: out[b] = bout + sum of 8 slot contributions ----------------
__global__ void k_final(const float* __restrict__ bout, float* __restrict__ out,
                        int out_size) {
    int b = blockIdx.x * blockDim.x + threadIdx.x;
    float4 c0 = *(const float4*)(g_contrib + (size_t)b * 8);
    float4 c1 = *(const float4*)(g_contrib + (size_t)b * 8 + 4);
    out[b] = bout[0] + ((c0.x + c0.y) + (c0.z + c0.w)) +
                       ((c1.x + c1.y) + (c1.z + c1.w));
    if (b == 0)
        for (int i = Bq; i < out_size; i++) out[i] = g_aux;   // aux loss scalar
}

// ---------------- launch ----------------
extern "C" void kernel_launch(void* const* d_in, const int* in_sizes, int n_in,
                              void* d_out, int out_size) {
    const float* x    = (const float*)d_in[0];
    const float* Wq   = (const float*)d_in[1];
    const float* bq   = (const float*)d_in[2];
    const float* Wk   = (const float*)d_in[3];
    const float* bk   = (const float*)d_in[4];
    const float* Wg   = (const float*)d_in[5];
    const float* W1   = (const float*)d_in[6];
    const float* b1   = (const float*)d_in[7];
    const float* W2   = (const float*)d_in[8];
    const float* b2   = (const float*)d_in[9];
    const float* Wout = (const float*)d_in[10];
    const float* bout = (const float*)d_in[11];
    float* out = (float*)d_out;

    const int smFold = (128 * 132 + 128 * 64) * 4;  // 100,352 B
    const int smProj = (128 * 132 + 64 * 128) * 4;  // 100,352 B
    const int smExp  = 25600 * 4;                   // 102,400 B
    cudaFuncSetAttribute(k_fold,     cudaFuncAttributeMaxDynamicSharedMemorySize, smFold);
    cudaFuncSetAttribute(k_projgate, cudaFuncAttributeMaxDynamicSharedMemorySize, smProj);
    cudaFuncSetAttribute(k_expert,   cudaFuncAttributeMaxDynamicSharedMemorySize, smExp);

    k_init<<<1, 32>>>();
    k_fold<<<64, 256, smFold>>>(Wq, W1);
    k_fold_small<<<NBIN, 128>>>(bq, W1, b1, W2, b2, Wout, bk, Wg);
    dim3 gp(4, 128);
    k_projgate<<<gp, 256, smProj>>>(x, Wk, Wg);
    k_phase2<<<1, 64>>>();
    k_scatter<<<NSLOT / 256, 256>>>();
    k_expert<<<1056, 256, smExp>>>(x);
    k_final<<<Bq / 256, 256>>>(bout, out, out_size);
}

// round 16
// speedup vs baseline: 1.9697x; 1.0980x over previous
#include <cuda_runtime.h>
#include <cuda_bf16.h>
#include <cstdint>

// Problem constants
#define Bq    16384
#define Dd    128
#define Hh    4
#define Ee    8
#define Nn    65536        // B*H tokens
#define OD    32           // ODIM = D/H
#define NSLOT 131072       // Nn * TOPK
#define NGB   128          // gating blocks = batches of 128 b's
#define NBIN  32           // (expert, head) bins

typedef unsigned long long ull;

// packed f32x2 FMA (projgate; per-lane accumulation order identical to scalar)
#define FMA2(acc, a2, b2) \
    asm("fma.rn.f32x2 %0, %1, %2, %0;" : "+l"(acc) : "l"(a2), "l"(b2))
#define PACKBC(d, s) \
    asm("mov.b64 %0, {%1, %1};" : "=l"(d) : "f"(s))

// warp-level bf16 MMA, fp32 accumulate (sm_80+ base ISA; no arch suffix needed)
#define MMA16816(d, a0, a1, a2, a3, b0, b1) \
    asm volatile("mma.sync.aligned.m16n8k16.row.col.f32.bf16.bf16.f32 " \
        "{%0,%1,%2,%3}, {%4,%5,%6,%7}, {%8,%9}, {%0,%1,%2,%3};" \
        : "+f"((d)[0]), "+f"((d)[1]), "+f"((d)[2]), "+f"((d)[3]) \
        : "r"(a0), "r"(a1), "r"(a2), "r"(a3), "r"(b0), "r"(b1))

// ---------------- device scratch (no allocs allowed) ----------------
__device__ float g_bM[NBIN * Dd];        // folded bias (bq_h @ W1_e + b1_e)
__device__ float g_v [NBIN * Dd];        // W2_e @ Wout_chunk_h
__device__ float g_c [NBIN];             // b2_e . Wout_chunk_h
__device__ float g_bg[NBIN];             // bk_h @ Wg contribution to logit (e,h)
__device__ __align__(16) __nv_bfloat16 g_Mhi[NBIN * Dd * Dd];  // 1 MB : M^T hi [bin][hid][d]
__device__ __align__(16) __nv_bfloat16 g_Mlo[NBIN * Dd * Dd];  // 1 MB : M^T lo
__device__ int   g_topi [NSLOT];
__device__ float g_topw [NSLOT];
__device__ int   g_srank[NSLOT];         // rank within (b-block, bin)
__device__ int   g_blkcnt [NGB * NBIN];
__device__ int   g_blkbase[NGB * NBIN];  // per-bin exclusive prefix over blocks
__device__ int   g_off[NBIN + 1];
__device__ int   g_count[NBIN];
__device__ int   g_tileoff[NBIN + 1];
__device__ float g_sump[Ee];
__device__ int   g_cnt1[Ee];
__device__ float g_aux;
__device__ int   g_perm[NSLOT];          // bin-sorted list of (token*2+slot)
__device__ float g_contrib[NSLOT];       // per-slot weighted scalar contribution

// ---------------- init ----------------
__global__ void k_init() {
    int t = threadIdx.x;
    if (t < Ee) { g_sump[t] = 0.f; g_cnt1[t] = 0; }
}

// ---------------- fold: M = Wq_h @ W1_e, emitted as bf16 hi/lo M^T[hid][d] --------
// 64 blocks: (eh, half). 256 threads, 8x4 micro over a 128x64 slice of hid.
__global__ void k_fold(const float* __restrict__ Wq, const float* __restrict__ W1) {
    extern __shared__ float sm[];
    float* As = sm;               // 128 x 132 : Wq_h  (rows d, cols c)
    float* Bs = sm + 128 * 132;   // 128 x 64  : W1_e  (rows c, cols hid-slice)
    const int tid = threadIdx.x;
    const int bb = blockIdx.x;
    const int eh = bb >> 1;
    const int e  = eh >> 2, h = eh & 3;
    const int n0 = (bb & 1) * 64;

    for (int i = tid; i < 128 * 32; i += 256) {
        int r = i >> 5, c = (i & 31) << 2;
        *(float4*)(As + r * 132 + c) = *(const float4*)(Wq + (size_t)r * 512 + h * 128 + c);
    }
    for (int i = tid; i < 128 * 16; i += 256) {
        int r = i >> 4, c = (i & 15) << 2;
        *(float4*)(Bs + r * 64 + c) =
            *(const float4*)(W1 + (size_t)e * 16384 + (size_t)r * 128 + n0 + c);
    }
    __syncthreads();

    const int tx = tid & 15, ty = tid >> 4;
    float acc[8][4];
#pragma unroll
    for (int i = 0; i < 8; i++)
#pragma unroll
        for (int j = 0; j < 4; j++) acc[i][j] = 0.f;

#pragma unroll 8
    for (int k = 0; k < 128; k++) {
        float4 b = *(const float4*)(Bs + k * 64 + tx * 4);
#pragma unroll
        for (int i = 0; i < 8; i++) {
            float a = As[(ty + 16 * i) * 132 + k];
            acc[i][0] = fmaf(a, b.x, acc[i][0]);
            acc[i][1] = fmaf(a, b.y, acc[i][1]);
            acc[i][2] = fmaf(a, b.z, acc[i][2]);
            acc[i][3] = fmaf(a, b.w, acc[i][3]);
        }
    }

    // scatter hi/lo bf16 of M^T[hid][d]
#pragma unroll
    for (int i = 0; i < 8; i++) {
        int d = ty + 16 * i;
#pragma unroll
        for (int jj = 0; jj < 4; jj++) {
            int hid = n0 + tx * 4 + jj;
            float val = acc[i][jj];
            __nv_bfloat16 hb = __float2bfloat16(val);
            __nv_bfloat16 lb = __float2bfloat16(val - __bfloat162float(hb));
            size_t o = (size_t)eh * 16384 + (size_t)hid * 128 + d;
            g_Mhi[o] = hb;
            g_Mlo[o] = lb;
        }
    }
}

// ---------------- fold small: bM, v, c, bg per (e,h) ----------------
__global__ void k_fold_small(const float* __restrict__ bq, const float* __restrict__ W1,
                             const float* __restrict__ b1, const float* __restrict__ W2,
                             const float* __restrict__ b2, const float* __restrict__ Wout,
                             const float* __restrict__ bk, const float* __restrict__ Wg) {
    const int eh = blockIdx.x;
    const int e = eh >> 2, h = eh & 3;
    const int k = threadIdx.x;   // 0..127
    float s = b1[e * 128 + k];
    for (int j = 0; j < 128; j++)
        s = fmaf(bq[h * 128 + j], W1[(size_t)e * 16384 + (size_t)j * 128 + k], s);
    g_bM[eh * 128 + k] = s;
    float v = 0.f;
    for (int t = 0; t < 32; t++)
        v = fmaf(W2[(size_t)e * 4096 + (size_t)k * 32 + t], Wout[h * 32 + t], v);
    g_v[eh * 128 + k] = v;
    if (k == 0) {
        float c = 0.f;
        for (int t = 0; t < 32; t++)
            c = fmaf(b2[e * 32 + t], Wout[h * 32 + t], c);
        g_c[eh] = c;
    }
    if (k == 1) {
        float s2 = 0.f;
        for (int c = 0; c < 128; c++)
            s2 = fmaf(bk[h * 128 + c], Wg[c * 8 + e], s2);
        g_bg[eh] = s2;
    }
}

// ---------------- fused projection + gating (fp32-exact, unchanged) ---------------
__global__ void __launch_bounds__(256, 2)
k_projgate(const float* __restrict__ X, const float* __restrict__ Wk,
           const float* __restrict__ Wg) {
    extern __shared__ float sm[];
    float* As = sm;               // 128 x 132 : X tile, reused for C (gate feats)
    float* Bs = sm + 128 * 132;   // 64 x 128  : Wk k-chunk
    __shared__ int   srank[Ee];
    __shared__ float ssum [Ee];
    __shared__ int   scnt1[Ee];
    const int tid = threadIdx.x;
    const int h  = blockIdx.x;
    const int by = blockIdx.y;
    const int m0 = by * 128;
    const int n0 = h * 128;
    if (tid < Ee) { srank[tid] = 0; ssum[tid] = 0.f; scnt1[tid] = 0; }

    for (int i = tid; i < 128 * 32; i += 256) {
        int r = i >> 5, c = (i & 31) << 2;
        *(float4*)(As + r * 132 + c) = *(const float4*)(X + (size_t)(m0 + r) * Dd + c);
    }

    const int tx = tid & 15, ty = tid >> 4;
    ull acc2[8][4];
#pragma unroll
    for (int i = 0; i < 8; i++)
#pragma unroll
        for (int j = 0; j < 4; j++) acc2[i][j] = 0ull;

#pragma unroll
    for (int kc = 0; kc < 2; kc++) {
        for (int i = tid; i < 64 * 32; i += 256) {
            int r = i >> 5, c = (i & 31) << 2;
            *(float4*)(Bs + r * 128 + c) =
                *(const float4*)(Wk + (size_t)(kc * 64 + r) * 512 + n0 + c);
        }
        __syncthreads();
#pragma unroll 8
        for (int kk = 0; kk < 64; kk++) {
            ulonglong2 bp0 = *(const ulonglong2*)(Bs + kk * 128 + tx * 8);
            ulonglong2 bp1 = *(const ulonglong2*)(Bs + kk * 128 + tx * 8 + 4);
            int k = kc * 64 + kk;
#pragma unroll
            for (int i = 0; i < 8; i++) {
                float a = As[(ty + 16 * i) * 132 + k];
                ull ap; PACKBC(ap, a);
                FMA2(acc2[i][0], ap, bp0.x);
                FMA2(acc2[i][1], ap, bp0.y);
                FMA2(acc2[i][2], ap, bp1.x);
                FMA2(acc2[i][3], ap, bp1.y);
            }
        }
        __syncthreads();
    }

#pragma unroll
    for (int i = 0; i < 8; i++) {
        int m = ty + 16 * i;
#pragma unroll
        for (int j = 0; j < 4; j++)
            *(ull*)(As + m * 132 + tx * 8 + 2 * j) = acc2[i][j];
    }
    __syncthreads();

    const int lane = tid & 31, warp = tid >> 5;
    float wr[4][8];
#pragma unroll
    for (int i = 0; i < 4; i++)
#pragma unroll
        for (int e = 0; e < 8; e++)
            wr[i][e] = Wg[(lane * 4 + i) * 8 + e];
    float blg[8];
#pragma unroll
    for (int e = 0; e < 8; e++) blg[e] = g_bg[e * 4 + h];

    float lsum[8];
#pragma unroll
    for (int e = 0; e < 8; e++) lsum[e] = 0.f;

    for (int it = 0; it < 16; it++) {
        int m = warp * 16 + it;
        float4 gv = *(const float4*)(As + m * 132 + lane * 4);
        float p[8];
#pragma unroll
        for (int e = 0; e < 8; e++)
            p[e] = gv.x * wr[0][e] + gv.y * wr[1][e] + gv.z * wr[2][e] + gv.w * wr[3][e];
#pragma unroll
        for (int off = 16; off; off >>= 1)
#pragma unroll
            for (int e = 0; e < 8; e++)
                p[e] += __shfl_xor_sync(0xffffffffu, p[e], off);
#pragma unroll
        for (int e = 0; e < 8; e++) p[e] += blg[e];
        float mx = p[0];
#pragma unroll
        for (int e = 1; e < 8; e++) mx = fmaxf(mx, p[e]);
        float s = 0.f;
#pragma unroll
        for (int e = 0; e < 8; e++) { p[e] = __expf(p[e] - mx); s += p[e]; }
        float inv = 1.f / s;
#pragma unroll
        for (int e = 0; e < 8; e++) p[e] *= inv;
        int i1 = 0; float v1 = p[0];
#pragma unroll
        for (int e = 1; e < 8; e++) if (p[e] > v1) { v1 = p[e]; i1 = e; }
        int i2 = -1; float v2 = -1e30f;
#pragma unroll
        for (int e = 0; e < 8; e++) if (e != i1 && p[e] > v2) { v2 = p[e]; i2 = e; }
#pragma unroll
        for (int e = 0; e < 8; e++) lsum[e] += p[e];

        if (lane == 0) {
            int n = (m0 + m) * 4 + h;
            atomicAdd(&scnt1[i1], 1);
            int r1 = atomicAdd(&srank[i1], 1);
            int r2 = atomicAdd(&srank[i2], 1);
            float wsum = v1 + v2;
            g_topi[2 * n]     = i1;  g_topi[2 * n + 1] = i2;
            g_topw[2 * n]     = v1 / wsum;
            g_topw[2 * n + 1] = v2 / wsum;
            g_srank[2 * n]     = r1;
            g_srank[2 * n + 1] = r2;
        }
    }
    if (lane == 0)
#pragma unroll
        for (int e = 0; e < 8; e++) atomicAdd(&ssum[e], lsum[e]);
    __syncthreads();
    if (tid < Ee) {
        g_blkcnt[by * NBIN + tid * 4 + h] = srank[tid];
        atomicAdd(&g_sump[tid], ssum[tid]);
        atomicAdd(&g_cnt1[tid], scnt1[tid]);
    }
}

// ---------------- phase2: prefix sums, offsets, tile map, aux loss ----------------
__global__ void k_phase2() {
    const int tid = threadIdx.x;
    if (tid < NBIN) {
        int base = 0;
        for (int b = 0; b < NGB; b++) {
            int c = g_blkcnt[b * NBIN + tid];
            g_blkbase[b * NBIN + tid] = base;
            base += c;
        }
        g_count[tid] = base;
    }
    __syncthreads();
    if (tid == 0) {
        int off = 0, toff = 0;
        for (int bin = 0; bin < NBIN; bin++) {
            g_off[bin] = off; g_tileoff[bin] = toff;
            off  += g_count[bin];
            toff += (g_count[bin] + 127) >> 7;
        }
        g_off[NBIN] = off; g_tileoff[NBIN] = toff;
        float aux = 0.f;
        for (int e = 0; e < Ee; e++)
            aux += (float)g_cnt1[e] * g_sump[e];
        g_aux = (float)Ee * aux / ((float)Nn * (float)Nn);
    }
}

// ---------------- scatter slots into bin-sorted list ----------------
__global__ void k_scatter() {
    int idx = blockIdx.x * blockDim.x + threadIdx.x;
    if (idx >= NSLOT) return;
    int n = idx >> 1;
    int bin = g_topi[idx] * 4 + (n & 3);
    int gb  = idx >> 10;
    int pos = g_off[bin] + g_blkbase[gb * NBIN + bin] + g_srank[idx];
    g_perm[pos] = idx;
}

// ---------------- HMMA expert: gather+split-bf16 -> mma.sync 3-term -> epilogue ----
// one CTA = 128 slots of one bin; 8 warps, each warp: 16 slots x 128 hidden.
#define PADW   136              // bf16 per padded row (stride 68 words: conflict-free)
#define SM_AHI 0
#define SM_ALO 34816
#define SM_BHI 69632
#define SM_BLO 104448
#define SM_V   139264
#define SM_BM  139776
#define SM_W   140288
#define SM_ENC 140800
#define SM_TOT 141312

__global__ void __launch_bounds__(256, 1)
k_expert(const float* __restrict__ x) {
    extern __shared__ unsigned char smc[];
    const int tid = threadIdx.x;
    const int wid = tid >> 5, lane = tid & 31;

    const int t = blockIdx.x;
    if (t >= g_tileoff[NBIN]) return;
    int bin = 0;
#pragma unroll
    for (int i = 0; i < NBIN - 1; i++)
        if (t >= g_tileoff[i + 1]) bin++;
    const int tile = t - g_tileoff[bin];
    const int i0 = tile << 7;
    const int nvalid = min(128, g_count[bin] - i0);

    float* vSp = (float*)(smc + SM_V);
    float* bSp = (float*)(smc + SM_BM);
    float* sWp = (float*)(smc + SM_W);
    int*  sEnc = (int*)  (smc + SM_ENC);

    if (tid < 128) {
        int j = g_off[bin] + i0 + tid;
        if (j > NSLOT - 1) j = NSLOT - 1;   // tail rows: safe garbage, never stored
        int enc = g_perm[j];
        sEnc[tid] = enc;
        sWp[tid]  = g_topw[enc];
        vSp[tid]  = g_v [bin * 128 + tid];
        bSp[tid]  = g_bM[bin * 128 + tid];
    }
    __syncthreads();

    // B images: copy M^T hi/lo into padded rows (17 uint4 per 16-uint4 row)
    {
        const uint4* sh = (const uint4*)(g_Mhi + (size_t)bin * 16384);
        const uint4* sl = (const uint4*)(g_Mlo + (size_t)bin * 16384);
        uint4* dh = (uint4*)(smc + SM_BHI);
        uint4* dl = (uint4*)(smc + SM_BLO);
        for (int i = tid; i < 2048; i += 256) {
            int r = i >> 4, c = i & 15;
            dh[r * 17 + c] = sh[i];
            dl[r * 17 + c] = sl[i];
        }
    }
    // A images: gather token rows, split to bf16 hi/lo (2 threads per row)
    {
        int r = tid >> 1, half = tid & 1;
        const float* xr = x + (size_t)(sEnc[r] >> 3) * 128 + half * 64;
        __nv_bfloat16* ah = (__nv_bfloat16*)(smc + SM_AHI) + r * PADW + half * 64;
        __nv_bfloat16* al = (__nv_bfloat16*)(smc + SM_ALO) + r * PADW + half * 64;
#pragma unroll
        for (int i = 0; i < 16; i++) {
            float4 v4 = *(const float4*)(xr + i * 4);
            __nv_bfloat162 h0 = __floats2bfloat162_rn(v4.x, v4.y);
            __nv_bfloat162 h1 = __floats2bfloat162_rn(v4.z, v4.w);
            __nv_bfloat162 l0 = __floats2bfloat162_rn(v4.x - __bfloat162float(h0.x),
                                                      v4.y - __bfloat162float(h0.y));
            __nv_bfloat162 l1 = __floats2bfloat162_rn(v4.z - __bfloat162float(h1.x),
                                                      v4.w - __bfloat162float(h1.y));
            *(__nv_bfloat162*)(ah + i * 4)     = h0;
            *(__nv_bfloat162*)(ah + i * 4 + 2) = h1;
            *(__nv_bfloat162*)(al + i * 4)     = l0;
            *(__nv_bfloat162*)(al + i * 4 + 2) = l1;
        }
    }
    __syncthreads();

    const __nv_bfloat16* Ah = (const __nv_bfloat16*)(smc + SM_AHI);
    const __nv_bfloat16* Al = (const __nv_bfloat16*)(smc + SM_ALO);
    const __nv_bfloat16* Bh = (const __nv_bfloat16*)(smc + SM_BHI);
    const __nv_bfloat16* Bl = (const __nv_bfloat16*)(smc + SM_BLO);
    const int g   = lane >> 2;
    const int tig = lane & 3;
    const int ar0 = (wid * 16 + g) * PADW;
    const int ar1 = ar0 + 8 * PADW;

    float acc[16][4];
#pragma unroll
    for (int tt = 0; tt < 16; tt++)
#pragma unroll
        for (int j = 0; j < 4; j++) acc[tt][j] = 0.f;

#pragma unroll 1
    for (int ks = 0; ks < 8; ks++) {
        const int kc = ks * 16 + 2 * tig;
        uint32_t ah0 = *(const uint32_t*)(Ah + ar0 + kc);
        uint32_t ah1 = *(const uint32_t*)(Ah + ar1 + kc);
        uint32_t ah2 = *(const uint32_t*)(Ah + ar0 + kc + 8);
        uint32_t ah3 = *(const uint32_t*)(Ah + ar1 + kc + 8);
        uint32_t al0 = *(const uint32_t*)(Al + ar0 + kc);
        uint32_t al1 = *(const uint32_t*)(Al + ar1 + kc);
        uint32_t al2 = *(const uint32_t*)(Al + ar0 + kc + 8);
        uint32_t al3 = *(const uint32_t*)(Al + ar1 + kc + 8);
#pragma unroll
        for (int tt = 0; tt < 16; tt++) {
            int br = (tt * 8 + g) * PADW + kc;
            uint32_t b0 = *(const uint32_t*)(Bh + br);
            uint32_t b1 = *(const uint32_t*)(Bh + br + 8);
            MMA16816(acc[tt], ah0, ah1, ah2, ah3, b0, b1);
        }
#pragma unroll
        for (int tt = 0; tt < 16; tt++) {
            int br = (tt * 8 + g) * PADW + kc;
            uint32_t b0 = *(const uint32_t*)(Bl + br);
            uint32_t b1 = *(const uint32_t*)(Bl + br + 8);
            MMA16816(acc[tt], ah0, ah1, ah2, ah3, b0, b1);
        }
#pragma unroll
        for (int tt = 0; tt < 16; tt++) {
            int br = (tt * 8 + g) * PADW + kc;
            uint32_t b0 = *(const uint32_t*)(Bh + br);
            uint32_t b1 = *(const uint32_t*)(Bh + br + 8);
            MMA16816(acc[tt], al0, al1, al2, al3, b0, b1);
        }
    }

    // epilogue: lane owns rows (wid*16+g, +8), cols {8t+2tig, +1}
    float d0 = 0.f, d1 = 0.f;
#pragma unroll
    for (int tt = 0; tt < 16; tt++) {
        int c = tt * 8 + 2 * tig;
        float b0 = bSp[c], b1 = bSp[c + 1];
        float v0 = vSp[c], v1 = vSp[c + 1];
        d0 = fmaf(fmaxf(acc[tt][0] + b0, 0.f), v0, d0);
        d0 = fmaf(fmaxf(acc[tt][1] + b1, 0.f), v1, d0);
        d1 = fmaf(fmaxf(acc[tt][2] + b0, 0.f), v0, d1);
        d1 = fmaf(fmaxf(acc[tt][3] + b1, 0.f), v1, d1);
    }
    d0 += __shfl_xor_sync(0xffffffffu, d0, 1);
    d0 += __shfl_xor_sync(0xffffffffu, d0, 2);
    d1 += __shfl_xor_sync(0xffffffffu, d1, 1);
    d1 += __shfl_xor_sync(0xffffffffu, d1, 2);
    if (tig == 0) {
        float ceh = g_c[bin];
        int r0 = wid * 16 + g, r1 = r0 + 8;
        if (r0 < nvalid) g_contrib[sEnc[r0]] = sWp[r0] * (d0 + ceh);
        if (r1 < nvalid) g_contrib[sEnc[r1]] = sWp[r1] * (d1 + ceh);
    }
}

// ---------------- final: out[b] = bout + sum of 8 slot contributions ----------------
__global__ void k_final(const float* __restrict__ bout, float* __restrict__ out,
                        int out_size) {
    int b = blockIdx.x * blockDim.x + threadIdx.x;
    float4 c0 = *(const float4*)(g_contrib + (size_t)b * 8);
    float4 c1 = *(const float4*)(g_contrib + (size_t)b * 8 + 4);
    out[b] = bout[0] + ((c0.x + c0.y) + (c0.z + c0.w)) +
                       ((c1.x + c1.y) + (c1.z + c1.w));
    if (b == 0)
        for (int i = Bq; i < out_size; i++) out[i] = g_aux;   // aux loss scalar
}

// ---------------- launch ----------------
extern "C" void kernel_launch(void* const* d_in, const int* in_sizes, int n_in,
                              void* d_out, int out_size) {
    const float* x    = (const float*)d_in[0];
    const float* Wq   = (const float*)d_in[1];
    const float* bq   = (const float*)d_in[2];
    const float* Wk   = (const float*)d_in[3];
    const float* bk   = (const float*)d_in[4];
    const float* Wg   = (const float*)d_in[5];
    const float* W1   = (const float*)d_in[6];
    const float* b1   = (const float*)d_in[7];
    const float* W2   = (const float*)d_in[8];
    const float* b2   = (const float*)d_in[9];
    const float* Wout = (const float*)d_in[10];
    const float* bout = (const float*)d_in[11];
    float* out = (float*)d_out;

    const int smFold = (128 * 132 + 128 * 64) * 4;  // 100,352 B
    const int smProj = (128 * 132 + 64 * 128) * 4;  // 100,352 B
    cudaFuncSetAttribute(k_fold,     cudaFuncAttributeMaxDynamicSharedMemorySize, smFold);
    cudaFuncSetAttribute(k_projgate, cudaFuncAttributeMaxDynamicSharedMemorySize, smProj);
    cudaFuncSetAttribute(k_expert,   cudaFuncAttributeMaxDynamicSharedMemorySize, SM_TOT);

    k_init<<<1, 32>>>();
    k_fold<<<64, 256, smFold>>>(Wq, W1);
    k_fold_small<<<NBIN, 128>>>(bq, W1, b1, W2, b2, Wout, bk, Wg);
    dim3 gp(4, 128);
    k_projgate<<<gp, 256, smProj>>>(x, Wk, Wg);
    k_phase2<<<1, 64>>>();
    k_scatter<<<NSLOT / 256, 256>>>();
    k_expert<<<1056, 256, SM_TOT>>>(x);
    k_final<<<Bq / 256, 256>>>(bout, out, out_size);
}